// round 3
// baseline (speedup 1.0000x reference)
#include <cuda_runtime.h>

// Problem constants
#define Bn  2
#define Sn  2048
#define Dn  1024
#define Hn  8
#define DKn 128
#define Mn  (Bn*Sn)   // 4096

// Scratch (allocation-free rule: __device__ globals)
__device__ float g_qh[Bn*Hn*Sn*DKn];   // [B,H,S,DK]
__device__ float g_kh[Bn*Hn*Sn*DKn];
__device__ float g_vh[Bn*Hn*Sn*DKn];
__device__ float g_ctx[Mn*Dn];         // [B*S, D] (concat layout)

// ---------------------------------------------------------------------------
// Kernel 1: fused projections.  C = A[M,1024] @ W[1024,1024], written into
// heads layout [B,H,S,DK].  blockIdx.z selects q/k/v.  128x128x8 tile,
// 256 threads, 8x8 per thread.  Static smem only.
// ---------------------------------------------------------------------------
__global__ __launch_bounds__(256) void proj_kernel(
    const float* __restrict__ q, const float* __restrict__ k, const float* __restrict__ v,
    const float* __restrict__ Wq, const float* __restrict__ Wk, const float* __restrict__ Wv)
{
    const float* A; const float* W; float* C;
    if (blockIdx.z == 0)      { A = q; W = Wq; C = g_qh; }
    else if (blockIdx.z == 1) { A = k; W = Wk; C = g_kh; }
    else                      { A = v; W = Wv; C = g_vh; }

    __shared__ float As[8][128];   // [k][m]
    __shared__ float Bs[8][128];   // [k][n]

    const int tid = threadIdx.x;
    const int tx  = tid & 15, ty = tid >> 4;
    const int row0 = blockIdx.x * 128;
    const int col0 = blockIdx.y * 128;

    const int arow = tid >> 1,  acol = (tid & 1) * 4;   // A tile 128x8
    const int brow = tid >> 5,  bcol = (tid & 31) * 4;  // W tile 8x128

    float acc[8][8] = {};

    for (int kb = 0; kb < 1024; kb += 8) {
        float4 av = *(const float4*)(A + (size_t)(row0 + arow) * 1024 + kb + acol);
        float4 bv = *(const float4*)(W + (size_t)(kb + brow) * 1024 + col0 + bcol);
        __syncthreads();
        As[acol+0][arow] = av.x;
        As[acol+1][arow] = av.y;
        As[acol+2][arow] = av.z;
        As[acol+3][arow] = av.w;
        *(float4*)&Bs[brow][bcol] = bv;
        __syncthreads();
        #pragma unroll
        for (int kk = 0; kk < 8; kk++) {
            float a[8], b[8];
            *(float4*)&a[0] = *(const float4*)&As[kk][ty*8];
            *(float4*)&a[4] = *(const float4*)&As[kk][ty*8+4];
            *(float4*)&b[0] = *(const float4*)&Bs[kk][tx*8];
            *(float4*)&b[4] = *(const float4*)&Bs[kk][tx*8+4];
            #pragma unroll
            for (int i = 0; i < 8; i++)
                #pragma unroll
                for (int j = 0; j < 8; j++)
                    acc[i][j] = fmaf(a[i], b[j], acc[i][j]);
        }
    }

    // Epilogue: BN(128)==DK, so head index == blockIdx.y for the whole block.
    const int h = blockIdx.y;
    #pragma unroll
    for (int i = 0; i < 8; i++) {
        int m  = row0 + ty*8 + i;
        int b_ = m >> 11;          // / Sn
        int s_ = m & (Sn - 1);
        float* dst = C + (((size_t)(b_*Hn + h))*Sn + s_)*DKn + tx*8;
        float4 o0 = make_float4(acc[i][0], acc[i][1], acc[i][2], acc[i][3]);
        float4 o1 = make_float4(acc[i][4], acc[i][5], acc[i][6], acc[i][7]);
        *(float4*)(dst)     = o0;
        *(float4*)(dst + 4) = o1;
    }
}

// ---------------------------------------------------------------------------
// Kernel 2: flash attention, STATIC smem (<48KB) — no cudaFuncSetAttribute.
// 128 threads (16 tx x 8 ty), 32 q-rows per block, k-chunk 32.
// K and V time-share one 16KB buffer (K dead after scores).
// K stored with float4 XOR swizzle (column reads <=2-way);
// V stored unswizzled (row-wise float4 reads are conflict-free).
// Per thread: scores 4 rows x 2 kcols; PV acc 4 rows x 8 dk.
// ---------------------------------------------------------------------------
#define KC 32
#define PPITCH 36   // float4-aligned, breaks bank alignment across rows

__global__ __launch_bounds__(128) void attn_kernel()
{
    __shared__ float Qs[32*128];     // 16384 B
    __shared__ float KVs[32*128];    // 16384 B (K, then V)
    __shared__ float Ps[32*PPITCH];  //  4608 B

    const int tid = threadIdx.x;
    const int tx  = tid & 15, ty = tid >> 4;     // 16 x 8
    const int h = blockIdx.y, b = blockIdx.z;
    const int q0 = blockIdx.x * 32;

    const size_t head_off = ((size_t)(b*Hn + h)) * Sn * DKn;
    const float* Qg = g_qh + head_off;
    const float* Kg = g_kh + head_off;
    const float* Vg = g_vh + head_off;
    const float scale = 0.08838834764831845f;    // 1/sqrt(128)

    // Load Q tile 32x128 (1024 float4 / 128 threads = 8 each), pre-scaled.
    #pragma unroll
    for (int j = 0; j < 8; j++) {
        int fi = tid + j*128;
        int r  = fi >> 5, cc = fi & 31;
        float4 v4 = *(const float4*)(Qg + (size_t)(q0 + r)*DKn + cc*4);
        float* d = &Qs[r*128 + cc*4];
        d[0] = v4.x*scale; d[1] = v4.y*scale; d[2] = v4.z*scale; d[3] = v4.w*scale;
    }

    const int r0  = ty * 4;     // this thread's 4 q-rows
    const int kc0 = tx * 2;     // this thread's 2 k-cols
    const int sw  = (tx >> 1) & 7;  // K swizzle key: ((2tx+j)>>2)&7, same for j=0,1

    float rm[4], rl[4], acc[4][8];
    #pragma unroll
    for (int i = 0; i < 4; i++) {
        rm[i] = -1.0e30f; rl[i] = 0.0f;
        #pragma unroll
        for (int j = 0; j < 8; j++) acc[i][j] = 0.0f;
    }

    for (int kt = 0; kt < Sn; kt += KC) {
        __syncthreads();   // (a) prior PV reads of KVs(V) complete

        // Load K chunk, float4-swizzled by row: phys group = cc ^ ((r>>2)&7)
        #pragma unroll
        for (int j = 0; j < 8; j++) {
            int fi = tid + j*128;
            int r  = fi >> 5, cc = fi & 31;
            float4 kv = *(const float4*)(Kg + (size_t)(kt + r)*DKn + cc*4);
            int pg = cc ^ ((r >> 2) & 7);
            *(float4*)&KVs[r*128 + pg*4] = kv;
        }
        __syncthreads();   // (b) K (and Q on first iter) visible

        // Scores: sc[4][2] = Q(r0..r0+3) . K(kc0..kc0+1), vectorized over DK
        float sc[4][2] = {};
        {
            const float* k0p = &KVs[(kc0 + 0)*128];
            const float* k1p = &KVs[(kc0 + 1)*128];
            #pragma unroll
            for (int g = 0; g < 32; g++) {
                float4 k0 = *(const float4*)(k0p + ((g ^ sw) << 2));
                float4 k1 = *(const float4*)(k1p + ((g ^ sw) << 2));
                #pragma unroll
                for (int i = 0; i < 4; i++) {
                    float4 qv = *(const float4*)&Qs[(r0 + i)*128 + g*4];
                    sc[i][0] = fmaf(qv.x, k0.x, sc[i][0]);
                    sc[i][0] = fmaf(qv.y, k0.y, sc[i][0]);
                    sc[i][0] = fmaf(qv.z, k0.z, sc[i][0]);
                    sc[i][0] = fmaf(qv.w, k0.w, sc[i][0]);
                    sc[i][1] = fmaf(qv.x, k1.x, sc[i][1]);
                    sc[i][1] = fmaf(qv.y, k1.y, sc[i][1]);
                    sc[i][1] = fmaf(qv.z, k1.z, sc[i][1]);
                    sc[i][1] = fmaf(qv.w, k1.w, sc[i][1]);
                }
            }
        }

        // Online softmax per row: 16 tx lanes per row, half-warp butterflies.
        #pragma unroll
        for (int i = 0; i < 4; i++) {
            float tm = fmaxf(sc[i][0], sc[i][1]);
            #pragma unroll
            for (int off = 8; off >= 1; off >>= 1)
                tm = fmaxf(tm, __shfl_xor_sync(0xffffffffu, tm, off));
            float nm   = fmaxf(rm[i], tm);
            float corr = __expf(rm[i] - nm);
            rm[i] = nm;
            float p0 = __expf(sc[i][0] - nm);
            float p1 = __expf(sc[i][1] - nm);
            float ps = p0 + p1;
            #pragma unroll
            for (int off = 8; off >= 1; off >>= 1)
                ps += __shfl_xor_sync(0xffffffffu, ps, off);
            rl[i] = rl[i]*corr + ps;
            #pragma unroll
            for (int j = 0; j < 8; j++) acc[i][j] *= corr;
            Ps[(r0 + i)*PPITCH + kc0 + 0] = p0;
            Ps[(r0 + i)*PPITCH + kc0 + 1] = p1;
        }

        __syncthreads();   // (c) P visible; K reads done -> safe to overwrite KVs

        // Load V chunk, unswizzled (row-wise reads below are contiguous float4)
        #pragma unroll
        for (int j = 0; j < 8; j++) {
            int fi = tid + j*128;
            int r  = fi >> 5, cc = fi & 31;
            float4 vv = *(const float4*)(Vg + (size_t)(kt + r)*DKn + cc*4);
            *(float4*)&KVs[r*128 + cc*4] = vv;
        }
        __syncthreads();   // (d) V + P visible

        // acc += P[32x32] @ V[32x128]; rows r0.., dk cols tx*8..
        #pragma unroll
        for (int g = 0; g < 8; g++) {          // kk = g*4 + u
            float p4[4][4];
            #pragma unroll
            for (int i = 0; i < 4; i++)
                *(float4*)&p4[i][0] = *(const float4*)&Ps[(r0 + i)*PPITCH + g*4];
            #pragma unroll
            for (int u = 0; u < 4; u++) {
                int kk = g*4 + u;
                float4 va = *(const float4*)&KVs[kk*128 + tx*8];
                float4 vb = *(const float4*)&KVs[kk*128 + tx*8 + 4];
                float vr[8] = {va.x, va.y, va.z, va.w, vb.x, vb.y, vb.z, vb.w};
                #pragma unroll
                for (int i = 0; i < 4; i++) {
                    float p = p4[i][u];
                    #pragma unroll
                    for (int j = 0; j < 8; j++)
                        acc[i][j] = fmaf(p, vr[j], acc[i][j]);
                }
            }
        }
    }

    // Epilogue: ctx -> concat layout [B*S, D]
    #pragma unroll
    for (int i = 0; i < 4; i++) {
        float inv = 1.0f / rl[i];
        size_t m  = (size_t)b*Sn + q0 + r0 + i;
        float* dst = g_ctx + m*Dn + h*DKn + tx*8;
        float4 o0 = make_float4(acc[i][0]*inv, acc[i][1]*inv, acc[i][2]*inv, acc[i][3]*inv);
        float4 o1 = make_float4(acc[i][4]*inv, acc[i][5]*inv, acc[i][6]*inv, acc[i][7]*inv);
        *(float4*)(dst)     = o0;
        *(float4*)(dst + 4) = o1;
    }
}

// ---------------------------------------------------------------------------
// Kernel 3: out = ctx @ Wo^T + bo.  Wo is [N,K] row-major (nn.Linear).
// ---------------------------------------------------------------------------
__global__ __launch_bounds__(256) void outproj_kernel(
    const float* __restrict__ Wo, const float* __restrict__ bo, float* __restrict__ out)
{
    __shared__ float As[8][128];   // [k][m]
    __shared__ float Bs[8][128];   // [k][n]

    const int tid = threadIdx.x;
    const int tx  = tid & 15, ty = tid >> 4;
    const int row0 = blockIdx.x * 128;
    const int col0 = blockIdx.y * 128;

    const int arow = tid >> 1, acol = (tid & 1) * 4;   // ctx tile 128x8
    const int wrow = tid >> 1, wcol = (tid & 1) * 4;   // Wo tile 128(n)x8(k)

    float acc[8][8] = {};

    for (int kb = 0; kb < 1024; kb += 8) {
        float4 av = *(const float4*)(g_ctx + (size_t)(row0 + arow) * 1024 + kb + acol);
        float4 wv = *(const float4*)(Wo    + (size_t)(col0 + wrow) * 1024 + kb + wcol);
        __syncthreads();
        As[acol+0][arow] = av.x;
        As[acol+1][arow] = av.y;
        As[acol+2][arow] = av.z;
        As[acol+3][arow] = av.w;
        Bs[wcol+0][wrow] = wv.x;
        Bs[wcol+1][wrow] = wv.y;
        Bs[wcol+2][wrow] = wv.z;
        Bs[wcol+3][wrow] = wv.w;
        __syncthreads();
        #pragma unroll
        for (int kk = 0; kk < 8; kk++) {
            float a[8], bfr[8];
            *(float4*)&a[0]   = *(const float4*)&As[kk][ty*8];
            *(float4*)&a[4]   = *(const float4*)&As[kk][ty*8+4];
            *(float4*)&bfr[0] = *(const float4*)&Bs[kk][tx*8];
            *(float4*)&bfr[4] = *(const float4*)&Bs[kk][tx*8+4];
            #pragma unroll
            for (int i = 0; i < 8; i++)
                #pragma unroll
                for (int j = 0; j < 8; j++)
                    acc[i][j] = fmaf(a[i], bfr[j], acc[i][j]);
        }
    }

    #pragma unroll
    for (int i = 0; i < 8; i++) {
        int m = row0 + ty*8 + i;
        float* dst = out + (size_t)m*1024 + col0 + tx*8;
        #pragma unroll
        for (int j = 0; j < 8; j++)
            dst[j] = acc[i][j] + bo[col0 + tx*8 + j];
    }
}

// ---------------------------------------------------------------------------
extern "C" void kernel_launch(void* const* d_in, const int* in_sizes, int n_in,
                              void* d_out, int out_size)
{
    const float* q  = (const float*)d_in[0];
    const float* k  = (const float*)d_in[1];
    const float* v  = (const float*)d_in[2];
    const float* Wq = (const float*)d_in[3];
    const float* Wk = (const float*)d_in[4];
    const float* Wv = (const float*)d_in[5];
    const float* Wo = (const float*)d_in[6];
    const float* bo = (const float*)d_in[7];
    float* out = (float*)d_out;

    proj_kernel<<<dim3(Mn/128, Dn/128, 3), 256>>>(q, k, v, Wq, Wk, Wv);
    attn_kernel<<<dim3(Sn/32, Hn, Bn), 128>>>();
    outproj_kernel<<<dim3(Mn/128, Dn/128), 256>>>(Wo, bo, out);
}

// round 6
// speedup vs baseline: 1.2447x; 1.2447x over previous
#include <cuda_runtime.h>
#include <cuda_bf16.h>
#include <cstdint>

// Problem constants
#define Bn  2
#define Sn  2048
#define Dn  1024
#define Hn  8
#define DKn 128
#define Mn  (Bn*Sn)   // 4096

// Scratch (allocation-free rule: __device__ globals)
__device__ float g_qh[Bn*Hn*Sn*DKn];   // [B,H,S,DK]
__device__ float g_kh[Bn*Hn*Sn*DKn];
__device__ float g_vh[Bn*Hn*Sn*DKn];
__device__ float g_ctx[Mn*Dn];         // [B*S, D] (concat layout)

// ===========================================================================
// mma.sync helpers (sm_100 base target: Ampere-lineage tensor core ISA)
// ===========================================================================
__device__ __forceinline__ uint32_t smem_u32(const void* p) {
    uint32_t a;
    asm("{ .reg .u64 t; cvta.to.shared.u64 t, %1; cvt.u32.u64 %0, t; }" : "=r"(a) : "l"(p));
    return a;
}
__device__ __forceinline__ void ldmA4(uint32_t addr, uint32_t* r) {
    asm volatile("ldmatrix.sync.aligned.m8n8.x4.shared.b16 {%0,%1,%2,%3}, [%4];"
                 : "=r"(r[0]), "=r"(r[1]), "=r"(r[2]), "=r"(r[3]) : "r"(addr));
}
__device__ __forceinline__ void ldmB2(uint32_t addr, uint32_t* r) {
    asm volatile("ldmatrix.sync.aligned.m8n8.x2.shared.b16 {%0,%1}, [%2];"
                 : "=r"(r[0]), "=r"(r[1]) : "r"(addr));
}
__device__ __forceinline__ void ldmB2t(uint32_t addr, uint32_t* r) {
    asm volatile("ldmatrix.sync.aligned.m8n8.x2.trans.shared.b16 {%0,%1}, [%2];"
                 : "=r"(r[0]), "=r"(r[1]) : "r"(addr));
}
__device__ __forceinline__ void mma16816(float* c, const uint32_t* a, const uint32_t* b) {
    asm volatile(
        "mma.sync.aligned.m16n8k16.row.col.f32.bf16.bf16.f32 "
        "{%0,%1,%2,%3}, {%4,%5,%6,%7}, {%8,%9}, {%0,%1,%2,%3};"
        : "+f"(c[0]), "+f"(c[1]), "+f"(c[2]), "+f"(c[3])
        : "r"(a[0]), "r"(a[1]), "r"(a[2]), "r"(a[3]), "r"(b[0]), "r"(b[1]));
}
// split (x0,x1) -> packed bf162 hi pair + bf162 lo-residual pair (products
// of hi/lo bf16 are exact in the fp32 accumulator; AlBl term dropped ~2^-18)
__device__ __forceinline__ void split2(float x0, float x1, uint32_t& hi, uint32_t& lo) {
    __nv_bfloat16 h0 = __float2bfloat16(x0);
    __nv_bfloat16 h1 = __float2bfloat16(x1);
    __nv_bfloat16 l0 = __float2bfloat16(x0 - __bfloat162float(h0));
    __nv_bfloat16 l1 = __float2bfloat16(x1 - __bfloat162float(h1));
    __nv_bfloat162 hp; hp.x = h0; hp.y = h1;
    __nv_bfloat162 lp; lp.x = l0; lp.y = l1;
    hi = *(uint32_t*)&hp;  lo = *(uint32_t*)&lp;
}

#define APITCHB 80    // bytes per row of [m][k]/[n][k] tiles (conflict-free ldmatrix)
#define KCH     32    // K-chunk
#define NCHK    (Dn / KCH)   // 32 chunks

// ---------------------------------------------------------------------------
// Kernel 1: fused projections via mma.sync bf16x3.  grid (32, 8, 3), 256 thr.
// C = A[4096,1024] @ W[1024,1024] -> heads layout.  B smem [k][n] + trans ldmatrix.
// ---------------------------------------------------------------------------
__global__ __launch_bounds__(256) void proj_mma(
    const float* __restrict__ q, const float* __restrict__ k, const float* __restrict__ v,
    const float* __restrict__ Wq, const float* __restrict__ Wk, const float* __restrict__ Wv)
{
    const float* A; const float* W; float* C;
    if (blockIdx.z == 0)      { A = q; W = Wq; C = g_qh; }
    else if (blockIdx.z == 1) { A = k; W = Wk; C = g_kh; }
    else                      { A = v; W = Wv; C = g_vh; }

    __shared__ __align__(16) char sAh[128*APITCHB];   // [m][k] hi, 80B pitch
    __shared__ __align__(16) char sAl[128*APITCHB];   // lo
    __shared__ __align__(16) char sBh[32*256];        // [k][n] hi, swizzled
    __shared__ __align__(16) char sBl[32*256];        // lo

    const int tid  = threadIdx.x;
    const int lane = tid & 31;
    const int wid  = tid >> 5;
    const int wm   = (wid >> 2) * 64;    // warp m offset (0,64)
    const int wn   = (wid & 3) * 32;     // warp n offset (0..96)
    const int row0 = blockIdx.x * 128;
    const int col0 = blockIdx.y * 128;

    const uint32_t aBh = smem_u32(sAh), aBl = smem_u32(sAl);
    const uint32_t bBh = smem_u32(sBh), bBl = smem_u32(sBl);

    float acc[4][4][4] = {};   // [mt][nt][c0..c3]

    for (int ch = 0; ch < NCHK; ch++) {
        const int kb = ch * KCH;
        __syncthreads();   // previous chunk's ldmatrix reads complete

        // ---- fill A 128x32 (4 float4 / thread, coalesced along k)
        #pragma unroll
        for (int j = 0; j < 4; j++) {
            int fi = tid + j*256;        // 0..1023
            int r  = fi >> 3;            // row
            int kq = (fi & 7) * 4;       // k offset
            float4 a4 = *(const float4*)(A + (size_t)(row0 + r)*1024 + kb + kq);
            uint32_t h0, l0, h1, l1;
            split2(a4.x, a4.y, h0, l0);
            split2(a4.z, a4.w, h1, l1);
            int off = r*APITCHB + (kq >> 3)*16 + (kq & 7)*2;
            *(uint32_t*)(sAh + off)     = h0;
            *(uint32_t*)(sAh + off + 4) = h1;
            *(uint32_t*)(sAl + off)     = l0;
            *(uint32_t*)(sAl + off + 4) = l1;
        }
        // ---- fill B 32(k)x128(n) (coalesced along n), XOR(k&7) 16B-group swizzle
        #pragma unroll
        for (int j = 0; j < 2; j++) {
            int gi = tid + j*256;        // 0..511 (16B groups)
            int kr = gi >> 4;            // k row 0..31
            int ng = gi & 15;            // n group
            const float* src = W + (size_t)(kb + kr)*1024 + col0 + ng*8;
            float4 w0 = *(const float4*)(src);
            float4 w1 = *(const float4*)(src + 4);
            uint32_t h0,l0,h1,l1,h2,l2,h3,l3;
            split2(w0.x, w0.y, h0, l0);
            split2(w0.z, w0.w, h1, l1);
            split2(w1.x, w1.y, h2, l2);
            split2(w1.z, w1.w, h3, l3);
            int off = kr*256 + ((ng ^ (kr & 7)) * 16);
            *(uint4*)(sBh + off) = make_uint4(h0, h1, h2, h3);
            *(uint4*)(sBl + off) = make_uint4(l0, l1, l2, l3);
        }
        __syncthreads();

        // ---- compute: 2 k16 steps x 3 terms x (4m x 4n) mma
        #pragma unroll
        for (int ks = 0; ks < 2; ks++) {
            uint32_t Ah[4][4], Al[4][4], Bh[4][2], Bl[4][2];
            int am = wm + (lane & 7) + ((lane >> 3) & 1) * 8;
            int ag = ks*2 + (lane >> 4);
            uint32_t aoff = am*APITCHB + ag*16;
            #pragma unroll
            for (int mt = 0; mt < 4; mt++) {
                ldmA4(aBh + aoff + mt*16*APITCHB, Ah[mt]);
                ldmA4(aBl + aoff + mt*16*APITCHB, Al[mt]);
            }
            int bk = ks*16 + (lane & 7) + ((lane >> 3) & 1) * 8;
            #pragma unroll
            for (int nt = 0; nt < 4; nt++) {
                int ngi = (wn >> 3) + nt;
                uint32_t boff = bk*256 + ((ngi ^ (bk & 7)) * 16);
                ldmB2t(bBh + boff, Bh[nt]);
                ldmB2t(bBl + boff, Bl[nt]);
            }
            #pragma unroll
            for (int mt = 0; mt < 4; mt++)
                #pragma unroll
                for (int nt = 0; nt < 4; nt++) {
                    mma16816(acc[mt][nt], Ah[mt], Bh[nt]);
                    mma16816(acc[mt][nt], Ah[mt], Bl[nt]);
                    mma16816(acc[mt][nt], Al[mt], Bh[nt]);
                }
        }
    }

    // ---- epilogue -> heads layout [B,H,S,DK]; head == blockIdx.y
    const int hh = blockIdx.y;
    #pragma unroll
    for (int mt = 0; mt < 4; mt++) {
        int m  = row0 + wm + mt*16 + (lane >> 2);
        int b_ = m >> 11;
        int s_ = m & (Sn - 1);
        float* base = C + (((size_t)(b_*Hn + hh))*Sn + s_)*DKn;
        #pragma unroll
        for (int nt = 0; nt < 4; nt++) {
            int col = wn + nt*8 + (lane & 3)*2;
            *(float2*)(base + col)           = make_float2(acc[mt][nt][0], acc[mt][nt][1]);
            *(float2*)(base + 8*DKn + col)   = make_float2(acc[mt][nt][2], acc[mt][nt][3]);
        }
    }
}

// ---------------------------------------------------------------------------
// Kernel 3: out = ctx @ Wo^T + bo via mma.sync bf16x3.  grid (32, 8), 256 thr.
// Wo is [N,K] row-major -> B smem [n][k] 80B pitch, non-trans ldmatrix.
// ---------------------------------------------------------------------------
__global__ __launch_bounds__(256) void outproj_mma(
    const float* __restrict__ Wo, const float* __restrict__ bo, float* __restrict__ out)
{
    __shared__ __align__(16) char sAh[128*APITCHB];
    __shared__ __align__(16) char sAl[128*APITCHB];
    __shared__ __align__(16) char sBh[128*APITCHB];
    __shared__ __align__(16) char sBl[128*APITCHB];

    const int tid  = threadIdx.x;
    const int lane = tid & 31;
    const int wid  = tid >> 5;
    const int wm   = (wid >> 2) * 64;
    const int wn   = (wid & 3) * 32;
    const int row0 = blockIdx.x * 128;
    const int col0 = blockIdx.y * 128;

    const uint32_t aBh = smem_u32(sAh), aBl = smem_u32(sAl);
    const uint32_t bBh = smem_u32(sBh), bBl = smem_u32(sBl);

    float acc[4][4][4] = {};

    for (int ch = 0; ch < NCHK; ch++) {
        const int kb = ch * KCH;
        __syncthreads();

        #pragma unroll
        for (int j = 0; j < 4; j++) {
            int fi = tid + j*256;
            int r  = fi >> 3;
            int kq = (fi & 7) * 4;
            int off = r*APITCHB + (kq >> 3)*16 + (kq & 7)*2;
            float4 a4 = *(const float4*)(g_ctx + (size_t)(row0 + r)*1024 + kb + kq);
            uint32_t h0, l0, h1, l1;
            split2(a4.x, a4.y, h0, l0);
            split2(a4.z, a4.w, h1, l1);
            *(uint32_t*)(sAh + off)     = h0;
            *(uint32_t*)(sAh + off + 4) = h1;
            *(uint32_t*)(sAl + off)     = l0;
            *(uint32_t*)(sAl + off + 4) = l1;
            float4 w4 = *(const float4*)(Wo + (size_t)(col0 + r)*1024 + kb + kq);
            split2(w4.x, w4.y, h0, l0);
            split2(w4.z, w4.w, h1, l1);
            *(uint32_t*)(sBh + off)     = h0;
            *(uint32_t*)(sBh + off + 4) = h1;
            *(uint32_t*)(sBl + off)     = l0;
            *(uint32_t*)(sBl + off + 4) = l1;
        }
        __syncthreads();

        #pragma unroll
        for (int ks = 0; ks < 2; ks++) {
            uint32_t Ah[4][4], Al[4][4], Bh[4][2], Bl[4][2];
            int am = wm + (lane & 7) + ((lane >> 3) & 1) * 8;
            int ag = ks*2 + (lane >> 4);
            uint32_t aoff = am*APITCHB + ag*16;
            #pragma unroll
            for (int mt = 0; mt < 4; mt++) {
                ldmA4(aBh + aoff + mt*16*APITCHB, Ah[mt]);
                ldmA4(aBl + aoff + mt*16*APITCHB, Al[mt]);
            }
            int bn = wn + (lane & 7);
            int bg = ks*2 + ((lane >> 3) & 1);
            uint32_t boff = bn*APITCHB + bg*16;
            #pragma unroll
            for (int nt = 0; nt < 4; nt++) {
                ldmB2(bBh + boff + nt*8*APITCHB, Bh[nt]);
                ldmB2(bBl + boff + nt*8*APITCHB, Bl[nt]);
            }
            #pragma unroll
            for (int mt = 0; mt < 4; mt++)
                #pragma unroll
                for (int nt = 0; nt < 4; nt++) {
                    mma16816(acc[mt][nt], Ah[mt], Bh[nt]);
                    mma16816(acc[mt][nt], Ah[mt], Bl[nt]);
                    mma16816(acc[mt][nt], Al[mt], Bh[nt]);
                }
        }
    }

    #pragma unroll
    for (int mt = 0; mt < 4; mt++) {
        int m = row0 + wm + mt*16 + (lane >> 2);
        float* dst = out + (size_t)m*1024 + col0;
        #pragma unroll
        for (int nt = 0; nt < 4; nt++) {
            int col = wn + nt*8 + (lane & 3)*2;
            float b0v = bo[col0 + col], b1v = bo[col0 + col + 1];
            *(float2*)(dst + col) =
                make_float2(acc[mt][nt][0] + b0v, acc[mt][nt][1] + b1v);
            *(float2*)(dst + 8*1024 + col) =
                make_float2(acc[mt][nt][2] + b0v, acc[mt][nt][3] + b1v);
        }
    }
}

// ---------------------------------------------------------------------------
// Kernel 2: flash attention (unchanged from round 3 — passing)
// ---------------------------------------------------------------------------
#define KC 32
#define PPITCH 36

__global__ __launch_bounds__(128) void attn_kernel()
{
    __shared__ float Qs[32*128];
    __shared__ float KVs[32*128];
    __shared__ float Ps[32*PPITCH];

    const int tid = threadIdx.x;
    const int tx  = tid & 15, ty = tid >> 4;
    const int h = blockIdx.y, b = blockIdx.z;
    const int q0 = blockIdx.x * 32;

    const size_t head_off = ((size_t)(b*Hn + h)) * Sn * DKn;
    const float* Qg = g_qh + head_off;
    const float* Kg = g_kh + head_off;
    const float* Vg = g_vh + head_off;
    const float scale = 0.08838834764831845f;

    #pragma unroll
    for (int j = 0; j < 8; j++) {
        int fi = tid + j*128;
        int r  = fi >> 5, cc = fi & 31;
        float4 v4 = *(const float4*)(Qg + (size_t)(q0 + r)*DKn + cc*4);
        float* d = &Qs[r*128 + cc*4];
        d[0] = v4.x*scale; d[1] = v4.y*scale; d[2] = v4.z*scale; d[3] = v4.w*scale;
    }

    const int r0  = ty * 4;
    const int kc0 = tx * 2;
    const int sw  = (tx >> 1) & 7;

    float rm[4], rl[4], acc[4][8];
    #pragma unroll
    for (int i = 0; i < 4; i++) {
        rm[i] = -1.0e30f; rl[i] = 0.0f;
        #pragma unroll
        for (int j = 0; j < 8; j++) acc[i][j] = 0.0f;
    }

    for (int kt = 0; kt < Sn; kt += KC) {
        __syncthreads();
        #pragma unroll
        for (int j = 0; j < 8; j++) {
            int fi = tid + j*128;
            int r  = fi >> 5, cc = fi & 31;
            float4 kv = *(const float4*)(Kg + (size_t)(kt + r)*DKn + cc*4);
            int pg = cc ^ ((r >> 2) & 7);
            *(float4*)&KVs[r*128 + pg*4] = kv;
        }
        __syncthreads();

        float sc[4][2] = {};
        {
            const float* k0p = &KVs[(kc0 + 0)*128];
            const float* k1p = &KVs[(kc0 + 1)*128];
            #pragma unroll
            for (int g = 0; g < 32; g++) {
                float4 k0 = *(const float4*)(k0p + ((g ^ sw) << 2));
                float4 k1 = *(const float4*)(k1p + ((g ^ sw) << 2));
                #pragma unroll
                for (int i = 0; i < 4; i++) {
                    float4 qv = *(const float4*)&Qs[(r0 + i)*128 + g*4];
                    sc[i][0] = fmaf(qv.x, k0.x, sc[i][0]);
                    sc[i][0] = fmaf(qv.y, k0.y, sc[i][0]);
                    sc[i][0] = fmaf(qv.z, k0.z, sc[i][0]);
                    sc[i][0] = fmaf(qv.w, k0.w, sc[i][0]);
                    sc[i][1] = fmaf(qv.x, k1.x, sc[i][1]);
                    sc[i][1] = fmaf(qv.y, k1.y, sc[i][1]);
                    sc[i][1] = fmaf(qv.z, k1.z, sc[i][1]);
                    sc[i][1] = fmaf(qv.w, k1.w, sc[i][1]);
                }
            }
        }

        #pragma unroll
        for (int i = 0; i < 4; i++) {
            float tm = fmaxf(sc[i][0], sc[i][1]);
            #pragma unroll
            for (int off = 8; off >= 1; off >>= 1)
                tm = fmaxf(tm, __shfl_xor_sync(0xffffffffu, tm, off));
            float nm   = fmaxf(rm[i], tm);
            float corr = __expf(rm[i] - nm);
            rm[i] = nm;
            float p0 = __expf(sc[i][0] - nm);
            float p1 = __expf(sc[i][1] - nm);
            float ps = p0 + p1;
            #pragma unroll
            for (int off = 8; off >= 1; off >>= 1)
                ps += __shfl_xor_sync(0xffffffffu, ps, off);
            rl[i] = rl[i]*corr + ps;
            #pragma unroll
            for (int j = 0; j < 8; j++) acc[i][j] *= corr;
            Ps[(r0 + i)*PPITCH + kc0 + 0] = p0;
            Ps[(r0 + i)*PPITCH + kc0 + 1] = p1;
        }

        __syncthreads();
        #pragma unroll
        for (int j = 0; j < 8; j++) {
            int fi = tid + j*128;
            int r  = fi >> 5, cc = fi & 31;
            float4 vv = *(const float4*)(Vg + (size_t)(kt + r)*DKn + cc*4);
            *(float4*)&KVs[r*128 + cc*4] = vv;
        }
        __syncthreads();

        #pragma unroll
        for (int g = 0; g < 8; g++) {
            float p4[4][4];
            #pragma unroll
            for (int i = 0; i < 4; i++)
                *(float4*)&p4[i][0] = *(const float4*)&Ps[(r0 + i)*PPITCH + g*4];
            #pragma unroll
            for (int u = 0; u < 4; u++) {
                int kk = g*4 + u;
                float4 va = *(const float4*)&KVs[kk*128 + tx*8];
                float4 vb = *(const float4*)&KVs[kk*128 + tx*8 + 4];
                float vr[8] = {va.x, va.y, va.z, va.w, vb.x, vb.y, vb.z, vb.w};
                #pragma unroll
                for (int i = 0; i < 4; i++) {
                    float p = p4[i][u];
                    #pragma unroll
                    for (int j = 0; j < 8; j++)
                        acc[i][j] = fmaf(p, vr[j], acc[i][j]);
                }
            }
        }
    }

    #pragma unroll
    for (int i = 0; i < 4; i++) {
        float inv = 1.0f / rl[i];
        size_t m  = (size_t)b*Sn + q0 + r0 + i;
        float* dst = g_ctx + m*Dn + h*DKn + tx*8;
        float4 o0 = make_float4(acc[i][0]*inv, acc[i][1]*inv, acc[i][2]*inv, acc[i][3]*inv);
        float4 o1 = make_float4(acc[i][4]*inv, acc[i][5]*inv, acc[i][6]*inv, acc[i][7]*inv);
        *(float4*)(dst)     = o0;
        *(float4*)(dst + 4) = o1;
    }
}

// ---------------------------------------------------------------------------
extern "C" void kernel_launch(void* const* d_in, const int* in_sizes, int n_in,
                              void* d_out, int out_size)
{
    const float* q  = (const float*)d_in[0];
    const float* k  = (const float*)d_in[1];
    const float* v  = (const float*)d_in[2];
    const float* Wq = (const float*)d_in[3];
    const float* Wk = (const float*)d_in[4];
    const float* Wv = (const float*)d_in[5];
    const float* Wo = (const float*)d_in[6];
    const float* bo = (const float*)d_in[7];
    float* out = (float*)d_out;

    proj_mma<<<dim3(Mn/128, Dn/128, 3), 256>>>(q, k, v, Wq, Wk, Wv);
    attn_kernel<<<dim3(Sn/32, Hn, Bn), 128>>>();
    outproj_mma<<<dim3(Mn/128, Dn/128), 256>>>(Wo, bo, out);
}

// round 7
// speedup vs baseline: 3.0927x; 2.4847x over previous
#include <cuda_runtime.h>
#include <cuda_bf16.h>
#include <cstdint>

// Problem constants
#define Bn  2
#define Sn  2048
#define Dn  1024
#define Hn  8
#define DKn 128
#define Mn  (Bn*Sn)   // 4096

// Scratch (allocation-free rule: __device__ globals)
__device__ float g_qh[Bn*Hn*Sn*DKn];   // [B,H,S,DK]
__device__ float g_kh[Bn*Hn*Sn*DKn];
__device__ float g_vh[Bn*Hn*Sn*DKn];
__device__ float g_ctx[Mn*Dn];         // [B*S, D] (concat layout)

// ===========================================================================
// mma.sync helpers (sm_100 base target: Ampere-lineage tensor core ISA)
// ===========================================================================
__device__ __forceinline__ uint32_t smem_u32(const void* p) {
    uint32_t a;
    asm("{ .reg .u64 t; cvta.to.shared.u64 t, %1; cvt.u32.u64 %0, t; }" : "=r"(a) : "l"(p));
    return a;
}
__device__ __forceinline__ void ldmA4(uint32_t addr, uint32_t* r) {
    asm volatile("ldmatrix.sync.aligned.m8n8.x4.shared.b16 {%0,%1,%2,%3}, [%4];"
                 : "=r"(r[0]), "=r"(r[1]), "=r"(r[2]), "=r"(r[3]) : "r"(addr));
}
__device__ __forceinline__ void ldmB2(uint32_t addr, uint32_t* r) {
    asm volatile("ldmatrix.sync.aligned.m8n8.x2.shared.b16 {%0,%1}, [%2];"
                 : "=r"(r[0]), "=r"(r[1]) : "r"(addr));
}
__device__ __forceinline__ void ldmB2t(uint32_t addr, uint32_t* r) {
    asm volatile("ldmatrix.sync.aligned.m8n8.x2.trans.shared.b16 {%0,%1}, [%2];"
                 : "=r"(r[0]), "=r"(r[1]) : "r"(addr));
}
__device__ __forceinline__ void mma16816(float* c, const uint32_t* a, const uint32_t* b) {
    asm volatile(
        "mma.sync.aligned.m16n8k16.row.col.f32.bf16.bf16.f32 "
        "{%0,%1,%2,%3}, {%4,%5,%6,%7}, {%8,%9}, {%0,%1,%2,%3};"
        : "+f"(c[0]), "+f"(c[1]), "+f"(c[2]), "+f"(c[3])
        : "r"(a[0]), "r"(a[1]), "r"(a[2]), "r"(a[3]), "r"(b[0]), "r"(b[1]));
}
// split (x0,x1) -> packed bf162 hi pair + bf162 lo-residual pair (products
// of hi/lo bf16 are exact in the fp32 accumulator; AlBl term dropped ~2^-18)
__device__ __forceinline__ void split2(float x0, float x1, uint32_t& hi, uint32_t& lo) {
    __nv_bfloat16 h0 = __float2bfloat16(x0);
    __nv_bfloat16 h1 = __float2bfloat16(x1);
    __nv_bfloat16 l0 = __float2bfloat16(x0 - __bfloat162float(h0));
    __nv_bfloat16 l1 = __float2bfloat16(x1 - __bfloat162float(h1));
    __nv_bfloat162 hp; hp.x = h0; hp.y = h1;
    __nv_bfloat162 lp; lp.x = l0; lp.y = l1;
    hi = *(uint32_t*)&hp;  lo = *(uint32_t*)&lp;
}
// split 8 consecutive floats into a 16B hi group and a 16B lo group
__device__ __forceinline__ void split8(const float* s, float scl, uint4& hi, uint4& lo) {
    float4 x0 = *(const float4*)(s);
    float4 x1 = *(const float4*)(s + 4);
    uint32_t h0,l0,h1,l1,h2,l2,h3,l3;
    split2(x0.x*scl, x0.y*scl, h0, l0);
    split2(x0.z*scl, x0.w*scl, h1, l1);
    split2(x1.x*scl, x1.y*scl, h2, l2);
    split2(x1.z*scl, x1.w*scl, h3, l3);
    hi = make_uint4(h0, h1, h2, h3);
    lo = make_uint4(l0, l1, l2, l3);
}

#define APITCHB 80    // bytes per row of [m][k]/[n][k] tiles (conflict-free ldmatrix)
#define KCH     32    // K-chunk (dense GEMMs)
#define NCHK    (Dn / KCH)   // 32 chunks

// ---------------------------------------------------------------------------
// Kernel 1: fused projections via mma.sync bf16x3 (unchanged from round 6).
// ---------------------------------------------------------------------------
__global__ __launch_bounds__(256) void proj_mma(
    const float* __restrict__ q, const float* __restrict__ k, const float* __restrict__ v,
    const float* __restrict__ Wq, const float* __restrict__ Wk, const float* __restrict__ Wv)
{
    const float* A; const float* W; float* C;
    if (blockIdx.z == 0)      { A = q; W = Wq; C = g_qh; }
    else if (blockIdx.z == 1) { A = k; W = Wk; C = g_kh; }
    else                      { A = v; W = Wv; C = g_vh; }

    __shared__ __align__(16) char sAh[128*APITCHB];
    __shared__ __align__(16) char sAl[128*APITCHB];
    __shared__ __align__(16) char sBh[32*256];
    __shared__ __align__(16) char sBl[32*256];

    const int tid  = threadIdx.x;
    const int lane = tid & 31;
    const int wid  = tid >> 5;
    const int wm   = (wid >> 2) * 64;
    const int wn   = (wid & 3) * 32;
    const int row0 = blockIdx.x * 128;
    const int col0 = blockIdx.y * 128;

    const uint32_t aBh = smem_u32(sAh), aBl = smem_u32(sAl);
    const uint32_t bBh = smem_u32(sBh), bBl = smem_u32(sBl);

    float acc[4][4][4] = {};

    for (int ch = 0; ch < NCHK; ch++) {
        const int kb = ch * KCH;
        __syncthreads();

        #pragma unroll
        for (int j = 0; j < 4; j++) {
            int fi = tid + j*256;
            int r  = fi >> 3;
            int kq = (fi & 7) * 4;
            float4 a4 = *(const float4*)(A + (size_t)(row0 + r)*1024 + kb + kq);
            uint32_t h0, l0, h1, l1;
            split2(a4.x, a4.y, h0, l0);
            split2(a4.z, a4.w, h1, l1);
            int off = r*APITCHB + (kq >> 3)*16 + (kq & 7)*2;
            *(uint32_t*)(sAh + off)     = h0;
            *(uint32_t*)(sAh + off + 4) = h1;
            *(uint32_t*)(sAl + off)     = l0;
            *(uint32_t*)(sAl + off + 4) = l1;
        }
        #pragma unroll
        for (int j = 0; j < 2; j++) {
            int gi = tid + j*256;
            int kr = gi >> 4;
            int ng = gi & 15;
            const float* src = W + (size_t)(kb + kr)*1024 + col0 + ng*8;
            uint4 hi, lo;
            split8(src, 1.0f, hi, lo);
            int off = kr*256 + ((ng ^ (kr & 7)) * 16);
            *(uint4*)(sBh + off) = hi;
            *(uint4*)(sBl + off) = lo;
        }
        __syncthreads();

        #pragma unroll
        for (int ks = 0; ks < 2; ks++) {
            uint32_t Ah[4][4], Al[4][4], Bh[4][2], Bl[4][2];
            int am = wm + (lane & 7) + ((lane >> 3) & 1) * 8;
            int ag = ks*2 + (lane >> 4);
            uint32_t aoff = am*APITCHB + ag*16;
            #pragma unroll
            for (int mt = 0; mt < 4; mt++) {
                ldmA4(aBh + aoff + mt*16*APITCHB, Ah[mt]);
                ldmA4(aBl + aoff + mt*16*APITCHB, Al[mt]);
            }
            int bk = ks*16 + (lane & 7) + ((lane >> 3) & 1) * 8;
            #pragma unroll
            for (int nt = 0; nt < 4; nt++) {
                int ngi = (wn >> 3) + nt;
                uint32_t boff = bk*256 + ((ngi ^ (bk & 7)) * 16);
                ldmB2t(bBh + boff, Bh[nt]);
                ldmB2t(bBl + boff, Bl[nt]);
            }
            #pragma unroll
            for (int mt = 0; mt < 4; mt++)
                #pragma unroll
                for (int nt = 0; nt < 4; nt++) {
                    mma16816(acc[mt][nt], Ah[mt], Bh[nt]);
                    mma16816(acc[mt][nt], Ah[mt], Bl[nt]);
                    mma16816(acc[mt][nt], Al[mt], Bh[nt]);
                }
        }
    }

    const int hh = blockIdx.y;
    #pragma unroll
    for (int mt = 0; mt < 4; mt++) {
        int m  = row0 + wm + mt*16 + (lane >> 2);
        int b_ = m >> 11;
        int s_ = m & (Sn - 1);
        float* base = C + (((size_t)(b_*Hn + hh))*Sn + s_)*DKn;
        #pragma unroll
        for (int nt = 0; nt < 4; nt++) {
            int col = wn + nt*8 + (lane & 3)*2;
            *(float2*)(base + col)           = make_float2(acc[mt][nt][0], acc[mt][nt][1]);
            *(float2*)(base + 8*DKn + col)   = make_float2(acc[mt][nt][2], acc[mt][nt][3]);
        }
    }
}

// ---------------------------------------------------------------------------
// Kernel 2: flash attention via mma.sync bf16x3.
// 128 threads = 4 warps; 64 q-rows/block (warp-m 16), K/V chunks of 32
// time-sharing one smem buffer.  Smem = exactly 48KB static.
// P converts from score accumulators directly into PV A-fragments (layouts
// coincide) — no smem round-trip.
// ---------------------------------------------------------------------------
__global__ __launch_bounds__(128) void attn_mma()
{
    __shared__ __align__(16) char sQh[64*256];    // 16KB  [m][k] swizzled
    __shared__ __align__(16) char sQl[64*256];    // 16KB
    __shared__ __align__(16) char sKVh[32*256];   //  8KB  K:[n][k] / V:[k][n]
    __shared__ __align__(16) char sKVl[32*256];   //  8KB

    const int tid  = threadIdx.x;
    const int lane = tid & 31;
    const int wid  = tid >> 5;           // 0..3
    const int h = blockIdx.y, b = blockIdx.z;
    const int q0 = blockIdx.x * 64;

    const size_t head_off = ((size_t)(b*Hn + h)) * Sn * DKn;
    const float* Qg = g_qh + head_off;
    const float* Kg = g_kh + head_off;
    const float* Vg = g_vh + head_off;
    const float scale = 0.08838834764831845f;   // 1/sqrt(128)

    const uint32_t qBh = smem_u32(sQh), qBl = smem_u32(sQl);
    const uint32_t kBh = smem_u32(sKVh), kBl = smem_u32(sKVl);

    // ---- fill Q (pre-scaled): 64 rows x 16 groups = 1024 groups, 8/thread
    #pragma unroll
    for (int j = 0; j < 8; j++) {
        int gi = tid + j*128;
        int r  = gi >> 4, g = gi & 15;
        uint4 hi, lo;
        split8(Qg + (size_t)(q0 + r)*DKn + g*8, scale, hi, lo);
        int off = r*256 + ((g ^ (r & 7)) * 16);
        *(uint4*)(sQh + off) = hi;
        *(uint4*)(sQl + off) = lo;
    }

    float acc[16][4] = {};        // PV accum: warp m16 x n128
    float rm[2] = {-1.0e30f, -1.0e30f}, rl[2] = {0.0f, 0.0f};

    for (int kt = 0; kt < Sn; kt += 32) {
        __syncthreads();   // prior chunk's V ldmatrix reads complete (and Q fill on it 0)

        // ---- fill K chunk 32x128: 512 groups, 4/thread
        #pragma unroll
        for (int j = 0; j < 4; j++) {
            int gi = tid + j*128;
            int r  = gi >> 4, g = gi & 15;
            uint4 hi, lo;
            split8(Kg + (size_t)(kt + r)*DKn + g*8, 1.0f, hi, lo);
            int off = r*256 + ((g ^ (r & 7)) * 16);
            *(uint4*)(sKVh + off) = hi;
            *(uint4*)(sKVl + off) = lo;
        }
        __syncthreads();

        // ---- QK^T: warp m16 x n32 x k128, bf16x3
        float sc[4][4] = {};
        #pragma unroll
        for (int ks = 0; ks < 8; ks++) {
            uint32_t Ah[4], Al[4];
            int arow = wid*16 + (lane & 7) + ((lane >> 3) & 1) * 8;
            int agrp = ks*2 + (lane >> 4);
            uint32_t aoff = arow*256 + ((agrp ^ (lane & 7)) * 16);
            ldmA4(qBh + aoff, Ah);
            ldmA4(qBl + aoff, Al);
            int bgrp = ks*2 + ((lane >> 3) & 1);
            #pragma unroll
            for (int nt = 0; nt < 4; nt++) {
                uint32_t Bh[2], Bl[2];
                int brow = nt*8 + (lane & 7);
                uint32_t boff = brow*256 + ((bgrp ^ (lane & 7)) * 16);
                ldmB2(kBh + boff, Bh);
                ldmB2(kBl + boff, Bl);
                mma16816(sc[nt], Ah, Bh);
                mma16816(sc[nt], Ah, Bl);
                mma16816(sc[nt], Al, Bh);
            }
        }

        // ---- online softmax (rows: set0 = lane>>2, set1 = +8)
        float mx0 = sc[0][0], mx1 = sc[0][2];
        #pragma unroll
        for (int nt = 0; nt < 4; nt++) {
            mx0 = fmaxf(mx0, fmaxf(sc[nt][0], sc[nt][1]));
            mx1 = fmaxf(mx1, fmaxf(sc[nt][2], sc[nt][3]));
        }
        mx0 = fmaxf(mx0, __shfl_xor_sync(0xffffffffu, mx0, 1));
        mx0 = fmaxf(mx0, __shfl_xor_sync(0xffffffffu, mx0, 2));
        mx1 = fmaxf(mx1, __shfl_xor_sync(0xffffffffu, mx1, 1));
        mx1 = fmaxf(mx1, __shfl_xor_sync(0xffffffffu, mx1, 2));
        float nm0 = fmaxf(rm[0], mx0), nm1 = fmaxf(rm[1], mx1);
        float cr0 = __expf(rm[0] - nm0), cr1 = __expf(rm[1] - nm1);
        rm[0] = nm0; rm[1] = nm1;
        float rs0 = 0.0f, rs1 = 0.0f;
        #pragma unroll
        for (int nt = 0; nt < 4; nt++) {
            sc[nt][0] = __expf(sc[nt][0] - nm0);
            sc[nt][1] = __expf(sc[nt][1] - nm0);
            sc[nt][2] = __expf(sc[nt][2] - nm1);
            sc[nt][3] = __expf(sc[nt][3] - nm1);
            rs0 += sc[nt][0] + sc[nt][1];
            rs1 += sc[nt][2] + sc[nt][3];
        }
        rs0 += __shfl_xor_sync(0xffffffffu, rs0, 1);
        rs0 += __shfl_xor_sync(0xffffffffu, rs0, 2);
        rs1 += __shfl_xor_sync(0xffffffffu, rs1, 1);
        rs1 += __shfl_xor_sync(0xffffffffu, rs1, 2);
        rl[0] = rl[0]*cr0 + rs0;
        rl[1] = rl[1]*cr1 + rs1;
        #pragma unroll
        for (int nt = 0; nt < 16; nt++) {
            acc[nt][0] *= cr0; acc[nt][1] *= cr0;
            acc[nt][2] *= cr1; acc[nt][3] *= cr1;
        }

        // ---- P -> A-fragments in registers (acc layout == A layout)
        uint32_t Ph[2][4], Pl[2][4];
        #pragma unroll
        for (int s = 0; s < 2; s++) {
            split2(sc[2*s][0],   sc[2*s][1],   Ph[s][0], Pl[s][0]);
            split2(sc[2*s][2],   sc[2*s][3],   Ph[s][1], Pl[s][1]);
            split2(sc[2*s+1][0], sc[2*s+1][1], Ph[s][2], Pl[s][2]);
            split2(sc[2*s+1][2], sc[2*s+1][3], Ph[s][3], Pl[s][3]);
        }

        __syncthreads();   // K ldmatrix reads done -> overwrite with V

        // ---- fill V chunk 32x128 (same layout; read as [k][n] via trans ldm)
        #pragma unroll
        for (int j = 0; j < 4; j++) {
            int gi = tid + j*128;
            int r  = gi >> 4, g = gi & 15;
            uint4 hi, lo;
            split8(Vg + (size_t)(kt + r)*DKn + g*8, 1.0f, hi, lo);
            int off = r*256 + ((g ^ (r & 7)) * 16);
            *(uint4*)(sKVh + off) = hi;
            *(uint4*)(sKVl + off) = lo;
        }
        __syncthreads();

        // ---- PV: warp m16 x n128 x k32, bf16x3 (V hi/lo, P hi/lo)
        #pragma unroll
        for (int s = 0; s < 2; s++) {
            int brow = s*16 + (lane & 7) + ((lane >> 3) & 1) * 8;
            #pragma unroll
            for (int nt = 0; nt < 16; nt++) {
                uint32_t Bh[2], Bl[2];
                uint32_t boff = brow*256 + ((nt ^ (lane & 7)) * 16);
                ldmB2t(kBh + boff, Bh);
                ldmB2t(kBl + boff, Bl);
                mma16816(acc[nt], Ph[s], Bh);
                mma16816(acc[nt], Ph[s], Bl);
                mma16816(acc[nt], Pl[s], Bh);
            }
        }
    }

    // ---- epilogue: normalize and write ctx (concat layout)
    float inv0 = 1.0f / rl[0], inv1 = 1.0f / rl[1];
    int m0 = q0 + wid*16 + (lane >> 2);
    float* d0 = g_ctx + (size_t)(b*Sn + m0)*Dn + h*DKn;
    float* d1 = d0 + 8*Dn;
    #pragma unroll
    for (int nt = 0; nt < 16; nt++) {
        int col = nt*8 + (lane & 3)*2;
        *(float2*)(d0 + col) = make_float2(acc[nt][0]*inv0, acc[nt][1]*inv0);
        *(float2*)(d1 + col) = make_float2(acc[nt][2]*inv1, acc[nt][3]*inv1);
    }
}

// ---------------------------------------------------------------------------
// Kernel 3: out = ctx @ Wo^T + bo via mma.sync bf16x3 (unchanged from round 6).
// ---------------------------------------------------------------------------
__global__ __launch_bounds__(256) void outproj_mma(
    const float* __restrict__ Wo, const float* __restrict__ bo, float* __restrict__ out)
{
    __shared__ __align__(16) char sAh[128*APITCHB];
    __shared__ __align__(16) char sAl[128*APITCHB];
    __shared__ __align__(16) char sBh[128*APITCHB];
    __shared__ __align__(16) char sBl[128*APITCHB];

    const int tid  = threadIdx.x;
    const int lane = tid & 31;
    const int wid  = tid >> 5;
    const int wm   = (wid >> 2) * 64;
    const int wn   = (wid & 3) * 32;
    const int row0 = blockIdx.x * 128;
    const int col0 = blockIdx.y * 128;

    const uint32_t aBh = smem_u32(sAh), aBl = smem_u32(sAl);
    const uint32_t bBh = smem_u32(sBh), bBl = smem_u32(sBl);

    float acc[4][4][4] = {};

    for (int ch = 0; ch < NCHK; ch++) {
        const int kb = ch * KCH;
        __syncthreads();

        #pragma unroll
        for (int j = 0; j < 4; j++) {
            int fi = tid + j*256;
            int r  = fi >> 3;
            int kq = (fi & 7) * 4;
            int off = r*APITCHB + (kq >> 3)*16 + (kq & 7)*2;
            float4 a4 = *(const float4*)(g_ctx + (size_t)(row0 + r)*1024 + kb + kq);
            uint32_t h0, l0, h1, l1;
            split2(a4.x, a4.y, h0, l0);
            split2(a4.z, a4.w, h1, l1);
            *(uint32_t*)(sAh + off)     = h0;
            *(uint32_t*)(sAh + off + 4) = h1;
            *(uint32_t*)(sAl + off)     = l0;
            *(uint32_t*)(sAl + off + 4) = l1;
            float4 w4 = *(const float4*)(Wo + (size_t)(col0 + r)*1024 + kb + kq);
            split2(w4.x, w4.y, h0, l0);
            split2(w4.z, w4.w, h1, l1);
            *(uint32_t*)(sBh + off)     = h0;
            *(uint32_t*)(sBh + off + 4) = h1;
            *(uint32_t*)(sBl + off)     = l0;
            *(uint32_t*)(sBl + off + 4) = l1;
        }
        __syncthreads();

        #pragma unroll
        for (int ks = 0; ks < 2; ks++) {
            uint32_t Ah[4][4], Al[4][4], Bh[4][2], Bl[4][2];
            int am = wm + (lane & 7) + ((lane >> 3) & 1) * 8;
            int ag = ks*2 + (lane >> 4);
            uint32_t aoff = am*APITCHB + ag*16;
            #pragma unroll
            for (int mt = 0; mt < 4; mt++) {
                ldmA4(aBh + aoff + mt*16*APITCHB, Ah[mt]);
                ldmA4(aBl + aoff + mt*16*APITCHB, Al[mt]);
            }
            int bn = wn + (lane & 7);
            int bg = ks*2 + ((lane >> 3) & 1);
            uint32_t boff = bn*APITCHB + bg*16;
            #pragma unroll
            for (int nt = 0; nt < 4; nt++) {
                ldmB2(bBh + boff + nt*8*APITCHB, Bh[nt]);
                ldmB2(bBl + boff + nt*8*APITCHB, Bl[nt]);
            }
            #pragma unroll
            for (int mt = 0; mt < 4; mt++)
                #pragma unroll
                for (int nt = 0; nt < 4; nt++) {
                    mma16816(acc[mt][nt], Ah[mt], Bh[nt]);
                    mma16816(acc[mt][nt], Ah[mt], Bl[nt]);
                    mma16816(acc[mt][nt], Al[mt], Bh[nt]);
                }
        }
    }

    #pragma unroll
    for (int mt = 0; mt < 4; mt++) {
        int m = row0 + wm + mt*16 + (lane >> 2);
        float* dst = out + (size_t)m*1024 + col0;
        #pragma unroll
        for (int nt = 0; nt < 4; nt++) {
            int col = wn + nt*8 + (lane & 3)*2;
            float b0v = bo[col0 + col], b1v = bo[col0 + col + 1];
            *(float2*)(dst + col) =
                make_float2(acc[mt][nt][0] + b0v, acc[mt][nt][1] + b1v);
            *(float2*)(dst + 8*1024 + col) =
                make_float2(acc[mt][nt][2] + b0v, acc[mt][nt][3] + b1v);
        }
    }
}

// ---------------------------------------------------------------------------
extern "C" void kernel_launch(void* const* d_in, const int* in_sizes, int n_in,
                              void* d_out, int out_size)
{
    const float* q  = (const float*)d_in[0];
    const float* k  = (const float*)d_in[1];
    const float* v  = (const float*)d_in[2];
    const float* Wq = (const float*)d_in[3];
    const float* Wk = (const float*)d_in[4];
    const float* Wv = (const float*)d_in[5];
    const float* Wo = (const float*)d_in[6];
    const float* bo = (const float*)d_in[7];
    float* out = (float*)d_out;

    proj_mma<<<dim3(Mn/128, Dn/128, 3), 256>>>(q, k, v, Wq, Wk, Wv);
    attn_mma<<<dim3(Sn/64, Hn, Bn), 128>>>();
    outproj_mma<<<dim3(Mn/128, Dn/128), 256>>>(Wo, bo, out);
}

// round 9
// speedup vs baseline: 3.8499x; 1.2448x over previous
#include <cuda_runtime.h>
#include <cuda_bf16.h>
#include <cstdint>

// Problem constants
#define Bn  2
#define Sn  2048
#define Dn  1024
#define Hn  8
#define DKn 128
#define Mn  (Bn*Sn)   // 4096

// Scratch (allocation-free rule: __device__ globals).  All bf16 hi/lo pairs
// packed as bf162 in uint32: heads rows of 64 u32 (=128 bf16), ctx rows of 512.
__device__ uint32_t g_qh_hi[Bn*Hn*Sn*64];
__device__ uint32_t g_qh_lo[Bn*Hn*Sn*64];
__device__ uint32_t g_kh_hi[Bn*Hn*Sn*64];
__device__ uint32_t g_kh_lo[Bn*Hn*Sn*64];
__device__ uint32_t g_vh_hi[Bn*Hn*Sn*64];
__device__ uint32_t g_vh_lo[Bn*Hn*Sn*64];
__device__ uint32_t g_ctx_hi[Mn*512];
__device__ uint32_t g_ctx_lo[Mn*512];

// ===========================================================================
// mma.sync helpers (sm_100 base target)
// ===========================================================================
__device__ __forceinline__ uint32_t smem_u32(const void* p) {
    uint32_t a;
    asm("{ .reg .u64 t; cvta.to.shared.u64 t, %1; cvt.u32.u64 %0, t; }" : "=r"(a) : "l"(p));
    return a;
}
__device__ __forceinline__ void ldmA4(uint32_t addr, uint32_t* r) {
    asm volatile("ldmatrix.sync.aligned.m8n8.x4.shared.b16 {%0,%1,%2,%3}, [%4];"
                 : "=r"(r[0]), "=r"(r[1]), "=r"(r[2]), "=r"(r[3]) : "r"(addr));
}
__device__ __forceinline__ void ldmB2(uint32_t addr, uint32_t* r) {
    asm volatile("ldmatrix.sync.aligned.m8n8.x2.shared.b16 {%0,%1}, [%2];"
                 : "=r"(r[0]), "=r"(r[1]) : "r"(addr));
}
__device__ __forceinline__ void ldmB2t(uint32_t addr, uint32_t* r) {
    asm volatile("ldmatrix.sync.aligned.m8n8.x2.trans.shared.b16 {%0,%1}, [%2];"
                 : "=r"(r[0]), "=r"(r[1]) : "r"(addr));
}
__device__ __forceinline__ void mma16816(float* c, const uint32_t* a, const uint32_t* b) {
    asm volatile(
        "mma.sync.aligned.m16n8k16.row.col.f32.bf16.bf16.f32 "
        "{%0,%1,%2,%3}, {%4,%5,%6,%7}, {%8,%9}, {%0,%1,%2,%3};"
        : "+f"(c[0]), "+f"(c[1]), "+f"(c[2]), "+f"(c[3])
        : "r"(a[0]), "r"(a[1]), "r"(a[2]), "r"(a[3]), "r"(b[0]), "r"(b[1]));
}
__device__ __forceinline__ void split2(float x0, float x1, uint32_t& hi, uint32_t& lo) {
    __nv_bfloat16 h0 = __float2bfloat16(x0);
    __nv_bfloat16 h1 = __float2bfloat16(x1);
    __nv_bfloat16 l0 = __float2bfloat16(x0 - __bfloat162float(h0));
    __nv_bfloat16 l1 = __float2bfloat16(x1 - __bfloat162float(h1));
    __nv_bfloat162 hp; hp.x = h0; hp.y = h1;
    __nv_bfloat162 lp; lp.x = l0; lp.y = l1;
    hi = *(uint32_t*)&hp;  lo = *(uint32_t*)&lp;
}

#define APITCHB 80    // bytes per row of [m][k]/[n][k] tiles (conflict-free ldmatrix)
#define KCH     32
#define NCHK    (Dn / KCH)

// ---------------------------------------------------------------------------
// Kernel 1: fused projections via mma.sync bf16x3.  Mainloop identical to
// round 6/7; epilogue now writes pre-split bf16 hi/lo heads (Q pre-scaled).
// ---------------------------------------------------------------------------
__global__ __launch_bounds__(256) void proj_mma(
    const float* __restrict__ q, const float* __restrict__ k, const float* __restrict__ v,
    const float* __restrict__ Wq, const float* __restrict__ Wk, const float* __restrict__ Wv)
{
    const float* A; const float* W; uint32_t* Chi; uint32_t* Clo; float oscale;
    if (blockIdx.z == 0)      { A = q; W = Wq; Chi = g_qh_hi; Clo = g_qh_lo;
                                oscale = 0.08838834764831845f; }
    else if (blockIdx.z == 1) { A = k; W = Wk; Chi = g_kh_hi; Clo = g_kh_lo; oscale = 1.0f; }
    else                      { A = v; W = Wv; Chi = g_vh_hi; Clo = g_vh_lo; oscale = 1.0f; }

    __shared__ __align__(16) char sAh[128*APITCHB];
    __shared__ __align__(16) char sAl[128*APITCHB];
    __shared__ __align__(16) char sBh[32*256];
    __shared__ __align__(16) char sBl[32*256];

    const int tid  = threadIdx.x;
    const int lane = tid & 31;
    const int wid  = tid >> 5;
    const int wm   = (wid >> 2) * 64;
    const int wn   = (wid & 3) * 32;
    const int row0 = blockIdx.x * 128;
    const int col0 = blockIdx.y * 128;

    const uint32_t aBh = smem_u32(sAh), aBl = smem_u32(sAl);
    const uint32_t bBh = smem_u32(sBh), bBl = smem_u32(sBl);

    float acc[4][4][4] = {};

    for (int ch = 0; ch < NCHK; ch++) {
        const int kb = ch * KCH;
        __syncthreads();

        #pragma unroll
        for (int j = 0; j < 4; j++) {
            int fi = tid + j*256;
            int r  = fi >> 3;
            int kq = (fi & 7) * 4;
            float4 a4 = *(const float4*)(A + (size_t)(row0 + r)*1024 + kb + kq);
            uint32_t h0, l0, h1, l1;
            split2(a4.x, a4.y, h0, l0);
            split2(a4.z, a4.w, h1, l1);
            int off = r*APITCHB + (kq >> 3)*16 + (kq & 7)*2;
            *(uint32_t*)(sAh + off)     = h0;
            *(uint32_t*)(sAh + off + 4) = h1;
            *(uint32_t*)(sAl + off)     = l0;
            *(uint32_t*)(sAl + off + 4) = l1;
        }
        #pragma unroll
        for (int j = 0; j < 2; j++) {
            int gi = tid + j*256;
            int kr = gi >> 4;
            int ng = gi & 15;
            const float* src = W + (size_t)(kb + kr)*1024 + col0 + ng*8;
            float4 w0 = *(const float4*)(src);
            float4 w1 = *(const float4*)(src + 4);
            uint32_t h0,l0,h1,l1,h2,l2,h3,l3;
            split2(w0.x, w0.y, h0, l0);
            split2(w0.z, w0.w, h1, l1);
            split2(w1.x, w1.y, h2, l2);
            split2(w1.z, w1.w, h3, l3);
            int off = kr*256 + ((ng ^ (kr & 7)) * 16);
            *(uint4*)(sBh + off) = make_uint4(h0, h1, h2, h3);
            *(uint4*)(sBl + off) = make_uint4(l0, l1, l2, l3);
        }
        __syncthreads();

        #pragma unroll
        for (int ks = 0; ks < 2; ks++) {
            uint32_t Ah[4][4], Al[4][4], Bh[4][2], Bl[4][2];
            int am = wm + (lane & 7) + ((lane >> 3) & 1) * 8;
            int ag = ks*2 + (lane >> 4);
            uint32_t aoff = am*APITCHB + ag*16;
            #pragma unroll
            for (int mt = 0; mt < 4; mt++) {
                ldmA4(aBh + aoff + mt*16*APITCHB, Ah[mt]);
                ldmA4(aBl + aoff + mt*16*APITCHB, Al[mt]);
            }
            int bk = ks*16 + (lane & 7) + ((lane >> 3) & 1) * 8;
            #pragma unroll
            for (int nt = 0; nt < 4; nt++) {
                int ngi = (wn >> 3) + nt;
                uint32_t boff = bk*256 + ((ngi ^ (bk & 7)) * 16);
                ldmB2t(bBh + boff, Bh[nt]);
                ldmB2t(bBl + boff, Bl[nt]);
            }
            #pragma unroll
            for (int mt = 0; mt < 4; mt++)
                #pragma unroll
                for (int nt = 0; nt < 4; nt++) {
                    mma16816(acc[mt][nt], Ah[mt], Bh[nt]);
                    mma16816(acc[mt][nt], Ah[mt], Bl[nt]);
                    mma16816(acc[mt][nt], Al[mt], Bh[nt]);
                }
        }
    }

    // ---- epilogue: split to bf16 hi/lo heads (head == blockIdx.y)
    const int hh = blockIdx.y;
    #pragma unroll
    for (int mt = 0; mt < 4; mt++) {
        int m  = row0 + wm + mt*16 + (lane >> 2);
        int b_ = m >> 11;
        int s_ = m & (Sn - 1);
        size_t rb = ((size_t)(b_*Hn + hh)*Sn + s_) * 64;
        #pragma unroll
        for (int nt = 0; nt < 4; nt++) {
            int cu = ((wn + nt*8) >> 1) + (lane & 3);
            uint32_t hv, lv;
            split2(acc[mt][nt][0]*oscale, acc[mt][nt][1]*oscale, hv, lv);
            Chi[rb + cu] = hv;  Clo[rb + cu] = lv;
            split2(acc[mt][nt][2]*oscale, acc[mt][nt][3]*oscale, hv, lv);
            Chi[rb + 8*64 + cu] = hv;  Clo[rb + 8*64 + cu] = lv;
        }
    }
}

// ---------------------------------------------------------------------------
// Kernel 2: flash attention via mma.sync bf16x3, v2.
// Pre-split inputs -> zero conversions in the loop; K/V in separate static
// buffers -> one batched fill + 2 syncs/chunk; Q-hi fragments in registers.
// Smem = 16KB (Q-lo resident) + 32KB (Khi|Klo|Vhi|Vlo) = 48KB static.
// ---------------------------------------------------------------------------
__global__ __launch_bounds__(128) void attn_mma()
{
    __shared__ __align__(16) char sQl[64*256];    // 16KB resident Q-lo
    __shared__ __align__(16) char sKV[4*8192];    // 32KB: Khi|Klo|Vhi|Vlo
    const int KH = 0, KL = 8192, VH = 16384, VL = 24576;

    const int tid  = threadIdx.x;
    const int lane = tid & 31;
    const int wid  = tid >> 5;
    const int h = blockIdx.y, b = blockIdx.z;
    const int q0 = blockIdx.x * 64;

    const size_t hb = ((size_t)(b*Hn + h)) * Sn * 64;
    const uint32_t* Qhi = g_qh_hi + hb;
    const uint32_t* Qlo = g_qh_lo + hb;
    const uint32_t* Khi = g_kh_hi + hb;
    const uint32_t* Klo = g_kh_lo + hb;
    const uint32_t* Vhi = g_vh_hi + hb;
    const uint32_t* Vlo = g_vh_lo + hb;

    const uint32_t qlB = smem_u32(sQl);
    const uint32_t kvB = smem_u32(sKV);

    // ---- one-time: stage Q-hi through sKV, hoist fragments to registers
    #pragma unroll
    for (int j = 0; j < 8; j++) {
        int gi = tid + j*128;
        int r  = gi >> 4, g = gi & 15;
        *(uint4*)(sKV + r*256 + ((g ^ (r & 7)) * 16)) =
            *(const uint4*)(Qhi + (size_t)(q0 + r)*64 + g*4);
    }
    __syncthreads();
    uint32_t Ah[8][4];
    const int arow = wid*16 + (lane & 7) + ((lane >> 3) & 1) * 8;
    #pragma unroll
    for (int ks = 0; ks < 8; ks++) {
        int agrp = ks*2 + (lane >> 4);
        ldmA4(kvB + arow*256 + ((agrp ^ (lane & 7)) * 16), Ah[ks]);
    }
    __syncthreads();   // Q-hi reads done before K/V fill overwrites sKV
    // ---- resident Q-lo (reads ordered by the loop's 2nd barrier)
    #pragma unroll
    for (int j = 0; j < 8; j++) {
        int gi = tid + j*128;
        int r  = gi >> 4, g = gi & 15;
        *(uint4*)(sQl + r*256 + ((g ^ (r & 7)) * 16)) =
            *(const uint4*)(Qlo + (size_t)(q0 + r)*64 + g*4);
    }

    float acc[16][4] = {};
    float rm[2] = {-1.0e30f, -1.0e30f}, rl[2] = {0.0f, 0.0f};

    for (int kt = 0; kt < Sn; kt += 32) {
        __syncthreads();   // prior chunk's K (QK) and V (PV) reads complete

        // ---- batched fill: K hi/lo + V hi/lo, pure copies, MLP=16
        #pragma unroll
        for (int j = 0; j < 4; j++) {
            int gi = tid + j*128;
            int r  = gi >> 4, g = gi & 15;
            int so = r*256 + ((g ^ (r & 7)) * 16);
            size_t go = (size_t)(kt + r)*64 + g*4;
            *(uint4*)(sKV + KH + so) = *(const uint4*)(Khi + go);
            *(uint4*)(sKV + KL + so) = *(const uint4*)(Klo + go);
            *(uint4*)(sKV + VH + so) = *(const uint4*)(Vhi + go);
            *(uint4*)(sKV + VL + so) = *(const uint4*)(Vlo + go);
        }
        __syncthreads();

        // ---- QK^T: warp m16 x n32 x k128, bf16x3 (Q-hi regs, Q-lo smem)
        float sc[4][4] = {};
        #pragma unroll
        for (int ks = 0; ks < 8; ks++) {
            uint32_t Al[4];
            int agrp = ks*2 + (lane >> 4);
            ldmA4(qlB + arow*256 + ((agrp ^ (lane & 7)) * 16), Al);
            int bgrp = ks*2 + ((lane >> 3) & 1);
            #pragma unroll
            for (int nt = 0; nt < 4; nt++) {
                uint32_t Bh[2], Bl[2];
                int brow = nt*8 + (lane & 7);
                uint32_t boff = brow*256 + ((bgrp ^ (lane & 7)) * 16);
                ldmB2(kvB + KH + boff, Bh);
                ldmB2(kvB + KL + boff, Bl);
                mma16816(sc[nt], Ah[ks], Bh);
                mma16816(sc[nt], Ah[ks], Bl);
                mma16816(sc[nt], Al, Bh);
            }
        }

        // ---- online softmax (rows: set0 = lane>>2, set1 = +8)
        float mx0 = sc[0][0], mx1 = sc[0][2];
        #pragma unroll
        for (int nt = 0; nt < 4; nt++) {
            mx0 = fmaxf(mx0, fmaxf(sc[nt][0], sc[nt][1]));
            mx1 = fmaxf(mx1, fmaxf(sc[nt][2], sc[nt][3]));
        }
        mx0 = fmaxf(mx0, __shfl_xor_sync(0xffffffffu, mx0, 1));
        mx0 = fmaxf(mx0, __shfl_xor_sync(0xffffffffu, mx0, 2));
        mx1 = fmaxf(mx1, __shfl_xor_sync(0xffffffffu, mx1, 1));
        mx1 = fmaxf(mx1, __shfl_xor_sync(0xffffffffu, mx1, 2));
        float nm0 = fmaxf(rm[0], mx0), nm1 = fmaxf(rm[1], mx1);
        float cr0 = __expf(rm[0] - nm0), cr1 = __expf(rm[1] - nm1);
        rm[0] = nm0; rm[1] = nm1;
        float rs0 = 0.0f, rs1 = 0.0f;
        #pragma unroll
        for (int nt = 0; nt < 4; nt++) {
            sc[nt][0] = __expf(sc[nt][0] - nm0);
            sc[nt][1] = __expf(sc[nt][1] - nm0);
            sc[nt][2] = __expf(sc[nt][2] - nm1);
            sc[nt][3] = __expf(sc[nt][3] - nm1);
            rs0 += sc[nt][0] + sc[nt][1];
            rs1 += sc[nt][2] + sc[nt][3];
        }
        rs0 += __shfl_xor_sync(0xffffffffu, rs0, 1);
        rs0 += __shfl_xor_sync(0xffffffffu, rs0, 2);
        rs1 += __shfl_xor_sync(0xffffffffu, rs1, 1);
        rs1 += __shfl_xor_sync(0xffffffffu, rs1, 2);
        rl[0] = rl[0]*cr0 + rs0;
        rl[1] = rl[1]*cr1 + rs1;
        #pragma unroll
        for (int nt = 0; nt < 16; nt++) {
            acc[nt][0] *= cr0; acc[nt][1] *= cr0;
            acc[nt][2] *= cr1; acc[nt][3] *= cr1;
        }

        // ---- P -> A-fragments in registers (acc layout == A layout)
        uint32_t Ph[2][4], Pl[2][4];
        #pragma unroll
        for (int s = 0; s < 2; s++) {
            split2(sc[2*s][0],   sc[2*s][1],   Ph[s][0], Pl[s][0]);
            split2(sc[2*s][2],   sc[2*s][3],   Ph[s][1], Pl[s][1]);
            split2(sc[2*s+1][0], sc[2*s+1][1], Ph[s][2], Pl[s][2]);
            split2(sc[2*s+1][2], sc[2*s+1][3], Ph[s][3], Pl[s][3]);
        }

        // ---- PV: warp m16 x n128 x k32 (V already filled; no extra sync)
        #pragma unroll
        for (int s = 0; s < 2; s++) {
            int brow = s*16 + (lane & 7) + ((lane >> 3) & 1) * 8;
            #pragma unroll
            for (int nt = 0; nt < 16; nt++) {
                uint32_t Bh[2], Bl[2];
                uint32_t boff = brow*256 + ((nt ^ (lane & 7)) * 16);
                ldmB2t(kvB + VH + boff, Bh);
                ldmB2t(kvB + VL + boff, Bl);
                mma16816(acc[nt], Ph[s], Bh);
                mma16816(acc[nt], Ph[s], Bl);
                mma16816(acc[nt], Pl[s], Bh);
            }
        }
    }

    // ---- epilogue: normalize, split, write ctx hi/lo (concat layout)
    float inv0 = 1.0f / rl[0], inv1 = 1.0f / rl[1];
    int m0 = q0 + wid*16 + (lane >> 2);
    size_t r0b = (size_t)(b*Sn + m0)*512 + h*64;
    #pragma unroll
    for (int nt = 0; nt < 16; nt++) {
        int cu = nt*4 + (lane & 3);
        uint32_t hv, lv;
        split2(acc[nt][0]*inv0, acc[nt][1]*inv0, hv, lv);
        g_ctx_hi[r0b + cu] = hv;  g_ctx_lo[r0b + cu] = lv;
        split2(acc[nt][2]*inv1, acc[nt][3]*inv1, hv, lv);
        g_ctx_hi[r0b + 8*512 + cu] = hv;  g_ctx_lo[r0b + 8*512 + cu] = lv;
    }
}

// ---------------------------------------------------------------------------
// Kernel 3: out = ctx @ Wo^T + bo.  A-fill is now a pure copy of pre-split
// ctx hi/lo; W-fill and mainloop unchanged from round 6/7.
// ---------------------------------------------------------------------------
__global__ __launch_bounds__(256) void outproj_mma(
    const float* __restrict__ Wo, const float* __restrict__ bo, float* __restrict__ out)
{
    __shared__ __align__(16) char sAh[128*APITCHB];
    __shared__ __align__(16) char sAl[128*APITCHB];
    __shared__ __align__(16) char sBh[128*APITCHB];
    __shared__ __align__(16) char sBl[128*APITCHB];

    const int tid  = threadIdx.x;
    const int lane = tid & 31;
    const int wid  = tid >> 5;
    const int wm   = (wid >> 2) * 64;
    const int wn   = (wid & 3) * 32;
    const int row0 = blockIdx.x * 128;
    const int col0 = blockIdx.y * 128;

    const uint32_t aBh = smem_u32(sAh), aBl = smem_u32(sAl);
    const uint32_t bBh = smem_u32(sBh), bBl = smem_u32(sBl);

    float acc[4][4][4] = {};

    for (int ch = 0; ch < NCHK; ch++) {
        const int kb = ch * KCH;
        __syncthreads();

        // A: copy pre-split ctx (512 16B-groups; 2/thread)
        #pragma unroll
        for (int j = 0; j < 2; j++) {
            int gi = tid + j*256;
            int r  = gi >> 2, g = gi & 3;
            int off = r*APITCHB + g*16;
            size_t go = (size_t)(row0 + r)*512 + (kb >> 1) + g*4;
            *(uint4*)(sAh + off) = *(const uint4*)(g_ctx_hi + go);
            *(uint4*)(sAl + off) = *(const uint4*)(g_ctx_lo + go);
        }
        // B: Wo fp32 -> split (as before)
        #pragma unroll
        for (int j = 0; j < 4; j++) {
            int fi = tid + j*256;
            int r  = fi >> 3;
            int kq = (fi & 7) * 4;
            int off = r*APITCHB + (kq >> 3)*16 + (kq & 7)*2;
            float4 w4 = *(const float4*)(Wo + (size_t)(col0 + r)*1024 + kb + kq);
            uint32_t h0, l0, h1, l1;
            split2(w4.x, w4.y, h0, l0);
            split2(w4.z, w4.w, h1, l1);
            *(uint32_t*)(sBh + off)     = h0;
            *(uint32_t*)(sBh + off + 4) = h1;
            *(uint32_t*)(sBl + off)     = l0;
            *(uint32_t*)(sBl + off + 4) = l1;
        }
        __syncthreads();

        #pragma unroll
        for (int ks = 0; ks < 2; ks++) {
            uint32_t Ah[4][4], Al[4][4], Bh[4][2], Bl[4][2];
            int am = wm + (lane & 7) + ((lane >> 3) & 1) * 8;
            int ag = ks*2 + (lane >> 4);
            uint32_t aoff = am*APITCHB + ag*16;
            #pragma unroll
            for (int mt = 0; mt < 4; mt++) {
                ldmA4(aBh + aoff + mt*16*APITCHB, Ah[mt]);
                ldmA4(aBl + aoff + mt*16*APITCHB, Al[mt]);
            }
            int bn = wn + (lane & 7);
            int bg = ks*2 + ((lane >> 3) & 1);
            uint32_t boff = bn*APITCHB + bg*16;
            #pragma unroll
            for (int nt = 0; nt < 4; nt++) {
                ldmB2(bBh + boff + nt*8*APITCHB, Bh[nt]);
                ldmB2(bBl + boff + nt*8*APITCHB, Bl[nt]);
            }
            #pragma unroll
            for (int mt = 0; mt < 4; mt++)
                #pragma unroll
                for (int nt = 0; nt < 4; nt++) {
                    mma16816(acc[mt][nt], Ah[mt], Bh[nt]);
                    mma16816(acc[mt][nt], Ah[mt], Bl[nt]);
                    mma16816(acc[mt][nt], Al[mt], Bh[nt]);
                }
        }
    }

    #pragma unroll
    for (int mt = 0; mt < 4; mt++) {
        int m = row0 + wm + mt*16 + (lane >> 2);
        float* dst = out + (size_t)m*1024 + col0;
        #pragma unroll
        for (int nt = 0; nt < 4; nt++) {
            int col = wn + nt*8 + (lane & 3)*2;
            float b0v = bo[col0 + col], b1v = bo[col0 + col + 1];
            *(float2*)(dst + col) =
                make_float2(acc[mt][nt][0] + b0v, acc[mt][nt][1] + b1v);
            *(float2*)(dst + 8*1024 + col) =
                make_float2(acc[mt][nt][2] + b0v, acc[mt][nt][3] + b1v);
        }
    }
}

// ---------------------------------------------------------------------------
extern "C" void kernel_launch(void* const* d_in, const int* in_sizes, int n_in,
                              void* d_out, int out_size)
{
    const float* q  = (const float*)d_in[0];
    const float* k  = (const float*)d_in[1];
    const float* v  = (const float*)d_in[2];
    const float* Wq = (const float*)d_in[3];
    const float* Wk = (const float*)d_in[4];
    const float* Wv = (const float*)d_in[5];
    const float* Wo = (const float*)d_in[6];
    const float* bo = (const float*)d_in[7];
    float* out = (float*)d_out;

    proj_mma<<<dim3(Mn/128, Dn/128, 3), 256>>>(q, k, v, Wq, Wk, Wv);
    attn_mma<<<dim3(Sn/64, Hn, Bn), 128>>>();
    outproj_mma<<<dim3(Mn/128, Dn/128), 256>>>(Wo, bo, out);
}

// round 10
// speedup vs baseline: 3.9241x; 1.0193x over previous
#include <cuda_runtime.h>
#include <cuda_bf16.h>
#include <cstdint>

// Problem constants
#define Bn  2
#define Sn  2048
#define Dn  1024
#define Hn  8
#define Mn  (Bn*Sn)   // 4096

// ---------------------------------------------------------------------------
// Pre-split input pools (bf162-packed hi/lo of every fp32 input)
// ---------------------------------------------------------------------------
#define QOFF  0
#define KOFF  2097152
#define VOFF  4194304
#define WQOFF 6291456
#define WKOFF 6815744
#define WVOFF 7340032
#define WOOFF 7864320
#define INTOT 8388608
__device__ uint32_t g_in_hi[INTOT];
__device__ uint32_t g_in_lo[INTOT];
// heads (proj outputs): rows of 64 u32 (=128 bf16); ctx rows of 512 u32
__device__ uint32_t g_qh_hi[Bn*Hn*Sn*64];
__device__ uint32_t g_qh_lo[Bn*Hn*Sn*64];
__device__ uint32_t g_kh_hi[Bn*Hn*Sn*64];
__device__ uint32_t g_kh_lo[Bn*Hn*Sn*64];
__device__ uint32_t g_vh_hi[Bn*Hn*Sn*64];
__device__ uint32_t g_vh_lo[Bn*Hn*Sn*64];
__device__ uint32_t g_ctx_hi[Mn*512];
__device__ uint32_t g_ctx_lo[Mn*512];

// ===========================================================================
// helpers
// ===========================================================================
__device__ __forceinline__ uint32_t smem_u32(const void* p) {
    uint32_t a;
    asm("{ .reg .u64 t; cvta.to.shared.u64 t, %1; cvt.u32.u64 %0, t; }" : "=r"(a) : "l"(p));
    return a;
}
__device__ __forceinline__ void ldmA4(uint32_t addr, uint32_t* r) {
    asm volatile("ldmatrix.sync.aligned.m8n8.x4.shared.b16 {%0,%1,%2,%3}, [%4];"
                 : "=r"(r[0]), "=r"(r[1]), "=r"(r[2]), "=r"(r[3]) : "r"(addr));
}
__device__ __forceinline__ void ldmB2(uint32_t addr, uint32_t* r) {
    asm volatile("ldmatrix.sync.aligned.m8n8.x2.shared.b16 {%0,%1}, [%2];"
                 : "=r"(r[0]), "=r"(r[1]) : "r"(addr));
}
__device__ __forceinline__ void ldmB2t(uint32_t addr, uint32_t* r) {
    asm volatile("ldmatrix.sync.aligned.m8n8.x2.trans.shared.b16 {%0,%1}, [%2];"
                 : "=r"(r[0]), "=r"(r[1]) : "r"(addr));
}
__device__ __forceinline__ void mma16816(float* c, const uint32_t* a, const uint32_t* b) {
    asm volatile(
        "mma.sync.aligned.m16n8k16.row.col.f32.bf16.bf16.f32 "
        "{%0,%1,%2,%3}, {%4,%5,%6,%7}, {%8,%9}, {%0,%1,%2,%3};"
        : "+f"(c[0]), "+f"(c[1]), "+f"(c[2]), "+f"(c[3])
        : "r"(a[0]), "r"(a[1]), "r"(a[2]), "r"(a[3]), "r"(b[0]), "r"(b[1]));
}
__device__ __forceinline__ void split2(float x0, float x1, uint32_t& hi, uint32_t& lo) {
    __nv_bfloat16 h0 = __float2bfloat16(x0);
    __nv_bfloat16 h1 = __float2bfloat16(x1);
    __nv_bfloat16 l0 = __float2bfloat16(x0 - __bfloat162float(h0));
    __nv_bfloat16 l1 = __float2bfloat16(x1 - __bfloat162float(h1));
    __nv_bfloat162 hp; hp.x = h0; hp.y = h1;
    __nv_bfloat162 lp; lp.x = l0; lp.y = l1;
    hi = *(uint32_t*)&hp;  lo = *(uint32_t*)&lp;
}
// cp.async (Ampere-lineage, present in base sm_100)
__device__ __forceinline__ void cpa16(uint32_t dst, const void* src) {
    asm volatile("cp.async.cg.shared.global [%0], [%1], 16;" :: "r"(dst), "l"(src));
}
#define CPA_COMMIT() asm volatile("cp.async.commit_group;" ::: "memory")
#define CPA_WAIT1()  asm volatile("cp.async.wait_group 1;" ::: "memory")

#define APITCHB 80
#define KCH     32
#define NCHK    (Dn / KCH)

// ---------------------------------------------------------------------------
// Kernel 0: pre-split fp32 -> bf16 hi/lo pools (adjacent-pair packing)
// ---------------------------------------------------------------------------
__global__ __launch_bounds__(256) void split_pre(const float* __restrict__ src,
                                                 int dstoff, int npair)
{
    uint32_t* hi = g_in_hi + dstoff;
    uint32_t* lo = g_in_lo + dstoff;
    int i = blockIdx.x * blockDim.x + threadIdx.x;
    int stride = gridDim.x * blockDim.x;
    for (; i < npair; i += stride) {
        float2 x = ((const float2*)src)[i];
        split2(x.x, x.y, hi[i], lo[i]);
    }
}

// ---------------------------------------------------------------------------
// Kernel 1: fused projections, cp.async double-buffered.
// Stage layout (36864 B/stage): Ah@0(10240) Al@10240 Bh@20480(8192) Bl@28672
// ---------------------------------------------------------------------------
#define P_STAGE 36864
#define P_SMEM  (2*P_STAGE)

__global__ __launch_bounds__(256) void proj_mma()
{
    extern __shared__ char sm[];
    const uint32_t *Ahi, *Alo, *Whi, *Wlo;
    uint32_t *Chi, *Clo; float oscale;
    if (blockIdx.z == 0)      { Ahi = g_in_hi+QOFF; Alo = g_in_lo+QOFF;
                                Whi = g_in_hi+WQOFF; Wlo = g_in_lo+WQOFF;
                                Chi = g_qh_hi; Clo = g_qh_lo;
                                oscale = 0.08838834764831845f; }
    else if (blockIdx.z == 1) { Ahi = g_in_hi+KOFF; Alo = g_in_lo+KOFF;
                                Whi = g_in_hi+WKOFF; Wlo = g_in_lo+WKOFF;
                                Chi = g_kh_hi; Clo = g_kh_lo; oscale = 1.0f; }
    else                      { Ahi = g_in_hi+VOFF; Alo = g_in_lo+VOFF;
                                Whi = g_in_hi+WVOFF; Wlo = g_in_lo+WVOFF;
                                Chi = g_vh_hi; Clo = g_vh_lo; oscale = 1.0f; }

    const int tid  = threadIdx.x;
    const int lane = tid & 31;
    const int wid  = tid >> 5;
    const int wm   = (wid >> 2) * 64;
    const int wn   = (wid & 3) * 32;
    const int row0 = blockIdx.x * 128;
    const int col0u = blockIdx.y * 64;   // u32 col offset (128 floats / 2)
    const uint32_t smU = smem_u32(sm);

    float acc[4][4][4] = {};

    // fill for chunk ch into stage s
    auto fill = [&](int ch, int s) {
        const int kbu = ch * (KCH/2);           // u32 k offset
        const uint32_t base = smU + s*P_STAGE;
        #pragma unroll
        for (int j = 0; j < 2; j++) {
            int gi = tid + j*256;
            int r = gi >> 2, g = gi & 3;
            uint32_t d = base + r*APITCHB + g*16;
            size_t so = (size_t)(row0 + r)*512 + kbu + g*4;
            cpa16(d,          Ahi + so);
            cpa16(d + 10240,  Alo + so);
        }
        #pragma unroll
        for (int j = 0; j < 2; j++) {
            int gi = tid + j*256;
            int kr = gi >> 4, ng = gi & 15;
            uint32_t d = base + 20480 + kr*256 + ((ng ^ (kr & 7)) * 16);
            size_t so = (size_t)(ch*KCH + kr)*512 + col0u + ng*4;
            cpa16(d,         Whi + so);
            cpa16(d + 8192,  Wlo + so);
        }
    };

    fill(0, 0);
    CPA_COMMIT();

    for (int ch = 0; ch < NCHK; ch++) {
        if (ch + 1 < NCHK) fill(ch + 1, (ch + 1) & 1);
        CPA_COMMIT();          // (empty group on last iter keeps accounting exact)
        CPA_WAIT1();
        __syncthreads();

        const uint32_t base = smU + (ch & 1)*P_STAGE;
        const uint32_t aBh = base, aBl = base + 10240;
        const uint32_t bBh = base + 20480, bBl = base + 28672;

        #pragma unroll
        for (int ks = 0; ks < 2; ks++) {
            uint32_t Ah[4][4], Al[4][4], Bh[4][2], Bl[4][2];
            int am = wm + (lane & 7) + ((lane >> 3) & 1) * 8;
            int ag = ks*2 + (lane >> 4);
            uint32_t aoff = am*APITCHB + ag*16;
            #pragma unroll
            for (int mt = 0; mt < 4; mt++) {
                ldmA4(aBh + aoff + mt*16*APITCHB, Ah[mt]);
                ldmA4(aBl + aoff + mt*16*APITCHB, Al[mt]);
            }
            int bk = ks*16 + (lane & 7) + ((lane >> 3) & 1) * 8;
            #pragma unroll
            for (int nt = 0; nt < 4; nt++) {
                int ngi = (wn >> 3) + nt;
                uint32_t boff = bk*256 + ((ngi ^ (bk & 7)) * 16);
                ldmB2t(bBh + boff, Bh[nt]);
                ldmB2t(bBl + boff, Bl[nt]);
            }
            #pragma unroll
            for (int mt = 0; mt < 4; mt++)
                #pragma unroll
                for (int nt = 0; nt < 4; nt++) {
                    mma16816(acc[mt][nt], Ah[mt], Bh[nt]);
                    mma16816(acc[mt][nt], Ah[mt], Bl[nt]);
                    mma16816(acc[mt][nt], Al[mt], Bh[nt]);
                }
        }
        __syncthreads();       // stage safe to refill (for ch+2)
    }

    // epilogue: split to bf16 hi/lo heads (head == blockIdx.y)
    #pragma unroll
    for (int mt = 0; mt < 4; mt++) {
        int m  = row0 + wm + mt*16 + (lane >> 2);
        int b_ = m >> 11;
        int s_ = m & (Sn - 1);
        size_t rb = ((size_t)(b_*Hn + blockIdx.y)*Sn + s_) * 64;
        #pragma unroll
        for (int nt = 0; nt < 4; nt++) {
            int cu = ((wn + nt*8) >> 1) + (lane & 3);
            uint32_t hv, lv;
            split2(acc[mt][nt][0]*oscale, acc[mt][nt][1]*oscale, hv, lv);
            Chi[rb + cu] = hv;  Clo[rb + cu] = lv;
            split2(acc[mt][nt][2]*oscale, acc[mt][nt][3]*oscale, hv, lv);
            Chi[rb + 8*64 + cu] = hv;  Clo[rb + 8*64 + cu] = lv;
        }
    }
}

// ---------------------------------------------------------------------------
// Kernel 2: flash attention, cp.async double-buffered K/V.
// Smem: Q-lo resident @0 (16KB); stages @16384 + s*32768: KH,KL,VH,VL (8KB ea)
// ---------------------------------------------------------------------------
#define A_SMEM (16384 + 2*32768)   // 81920

__global__ __launch_bounds__(128) void attn_mma()
{
    extern __shared__ char sm[];
    const int tid  = threadIdx.x;
    const int lane = tid & 31;
    const int wid  = tid >> 5;
    const int h = blockIdx.y, b = blockIdx.z;
    const int q0 = blockIdx.x * 64;

    const size_t hb = ((size_t)(b*Hn + h)) * Sn * 64;
    const uint32_t* Qhi = g_qh_hi + hb;
    const uint32_t* Qlo = g_qh_lo + hb;
    const uint32_t* Khi = g_kh_hi + hb;
    const uint32_t* Klo = g_kh_lo + hb;
    const uint32_t* Vhi = g_vh_hi + hb;
    const uint32_t* Vlo = g_vh_lo + hb;

    const uint32_t smU = smem_u32(sm);
    const uint32_t qlB = smU;

    // ---- stage Q-hi through stage-1 region, hoist fragments to registers
    #pragma unroll
    for (int j = 0; j < 8; j++) {
        int gi = tid + j*128;
        int r  = gi >> 4, g = gi & 15;
        *(uint4*)(sm + 16384 + 32768 + r*256 + ((g ^ (r & 7)) * 16)) =
            *(const uint4*)(Qhi + (size_t)(q0 + r)*64 + g*4);
    }
    __syncthreads();
    uint32_t Ah[8][4];
    const int arow = wid*16 + (lane & 7) + ((lane >> 3) & 1) * 8;
    #pragma unroll
    for (int ks = 0; ks < 8; ks++) {
        int agrp = ks*2 + (lane >> 4);
        ldmA4(smU + 16384 + 32768 + arow*256 + ((agrp ^ (lane & 7)) * 16), Ah[ks]);
    }
    // ---- resident Q-lo (plain; visible after pre-loop barrier)
    #pragma unroll
    for (int j = 0; j < 8; j++) {
        int gi = tid + j*128;
        int r  = gi >> 4, g = gi & 15;
        *(uint4*)(sm + r*256 + ((g ^ (r & 7)) * 16)) =
            *(const uint4*)(Qlo + (size_t)(q0 + r)*64 + g*4);
    }

    // fill K/V chunk into stage s
    auto fill = [&](int kt, int s) {
        const uint32_t base = smU + 16384 + s*32768;
        #pragma unroll
        for (int j = 0; j < 4; j++) {
            int gi = tid + j*128;
            int r  = gi >> 4, g = gi & 15;
            uint32_t so = r*256 + ((g ^ (r & 7)) * 16);
            size_t go = (size_t)(kt + r)*64 + g*4;
            cpa16(base + so,          Khi + go);
            cpa16(base + 8192 + so,   Klo + go);
            cpa16(base + 16384 + so,  Vhi + go);
            cpa16(base + 24576 + so,  Vlo + go);
        }
    };

    fill(0, 0);
    CPA_COMMIT();
    __syncthreads();   // Q-hi ldmatrix reads done before stage-1 refill (iter 0)

    float acc[16][4] = {};
    float rm[2] = {-1.0e30f, -1.0e30f}, rl[2] = {0.0f, 0.0f};

    const int NKT = Sn / 32;   // 64 chunks
    for (int ch = 0; ch < NKT; ch++) {
        if (ch + 1 < NKT) fill((ch + 1) * 32, (ch + 1) & 1);
        CPA_COMMIT();
        CPA_WAIT1();
        __syncthreads();

        const uint32_t base = smU + 16384 + (ch & 1)*32768;
        const uint32_t KH = base, KL = base + 8192, VH = base + 16384, VL = base + 24576;

        // ---- QK^T
        float sc[4][4] = {};
        #pragma unroll
        for (int ks = 0; ks < 8; ks++) {
            uint32_t Al[4];
            int agrp = ks*2 + (lane >> 4);
            ldmA4(qlB + arow*256 + ((agrp ^ (lane & 7)) * 16), Al);
            int bgrp = ks*2 + ((lane >> 3) & 1);
            #pragma unroll
            for (int nt = 0; nt < 4; nt++) {
                uint32_t Bh[2], Bl[2];
                int brow = nt*8 + (lane & 7);
                uint32_t boff = brow*256 + ((bgrp ^ (lane & 7)) * 16);
                ldmB2(KH + boff, Bh);
                ldmB2(KL + boff, Bl);
                mma16816(sc[nt], Ah[ks], Bh);
                mma16816(sc[nt], Ah[ks], Bl);
                mma16816(sc[nt], Al, Bh);
            }
        }

        // ---- online softmax
        float mx0 = sc[0][0], mx1 = sc[0][2];
        #pragma unroll
        for (int nt = 0; nt < 4; nt++) {
            mx0 = fmaxf(mx0, fmaxf(sc[nt][0], sc[nt][1]));
            mx1 = fmaxf(mx1, fmaxf(sc[nt][2], sc[nt][3]));
        }
        mx0 = fmaxf(mx0, __shfl_xor_sync(0xffffffffu, mx0, 1));
        mx0 = fmaxf(mx0, __shfl_xor_sync(0xffffffffu, mx0, 2));
        mx1 = fmaxf(mx1, __shfl_xor_sync(0xffffffffu, mx1, 1));
        mx1 = fmaxf(mx1, __shfl_xor_sync(0xffffffffu, mx1, 2));
        float nm0 = fmaxf(rm[0], mx0), nm1 = fmaxf(rm[1], mx1);
        float cr0 = __expf(rm[0] - nm0), cr1 = __expf(rm[1] - nm1);
        rm[0] = nm0; rm[1] = nm1;
        float rs0 = 0.0f, rs1 = 0.0f;
        #pragma unroll
        for (int nt = 0; nt < 4; nt++) {
            sc[nt][0] = __expf(sc[nt][0] - nm0);
            sc[nt][1] = __expf(sc[nt][1] - nm0);
            sc[nt][2] = __expf(sc[nt][2] - nm1);
            sc[nt][3] = __expf(sc[nt][3] - nm1);
            rs0 += sc[nt][0] + sc[nt][1];
            rs1 += sc[nt][2] + sc[nt][3];
        }
        rs0 += __shfl_xor_sync(0xffffffffu, rs0, 1);
        rs0 += __shfl_xor_sync(0xffffffffu, rs0, 2);
        rs1 += __shfl_xor_sync(0xffffffffu, rs1, 1);
        rs1 += __shfl_xor_sync(0xffffffffu, rs1, 2);
        rl[0] = rl[0]*cr0 + rs0;
        rl[1] = rl[1]*cr1 + rs1;
        #pragma unroll
        for (int nt = 0; nt < 16; nt++) {
            acc[nt][0] *= cr0; acc[nt][1] *= cr0;
            acc[nt][2] *= cr1; acc[nt][3] *= cr1;
        }

        // ---- P -> A-fragments in registers
        uint32_t Ph[2][4], Pl[2][4];
        #pragma unroll
        for (int s = 0; s < 2; s++) {
            split2(sc[2*s][0],   sc[2*s][1],   Ph[s][0], Pl[s][0]);
            split2(sc[2*s][2],   sc[2*s][3],   Ph[s][1], Pl[s][1]);
            split2(sc[2*s+1][0], sc[2*s+1][1], Ph[s][2], Pl[s][2]);
            split2(sc[2*s+1][2], sc[2*s+1][3], Ph[s][3], Pl[s][3]);
        }

        // ---- PV
        #pragma unroll
        for (int s = 0; s < 2; s++) {
            int brow = s*16 + (lane & 7) + ((lane >> 3) & 1) * 8;
            #pragma unroll
            for (int nt = 0; nt < 16; nt++) {
                uint32_t Bh[2], Bl[2];
                uint32_t boff = brow*256 + ((nt ^ (lane & 7)) * 16);
                ldmB2t(VH + boff, Bh);
                ldmB2t(VL + boff, Bl);
                mma16816(acc[nt], Ph[s], Bh);
                mma16816(acc[nt], Ph[s], Bl);
                mma16816(acc[nt], Pl[s], Bh);
            }
        }
        __syncthreads();   // stage safe to refill (for ch+2)
    }

    // ---- epilogue
    float inv0 = 1.0f / rl[0], inv1 = 1.0f / rl[1];
    int m0 = q0 + wid*16 + (lane >> 2);
    size_t r0b = (size_t)(b*Sn + m0)*512 + h*64;
    #pragma unroll
    for (int nt = 0; nt < 16; nt++) {
        int cu = nt*4 + (lane & 3);
        uint32_t hv, lv;
        split2(acc[nt][0]*inv0, acc[nt][1]*inv0, hv, lv);
        g_ctx_hi[r0b + cu] = hv;  g_ctx_lo[r0b + cu] = lv;
        split2(acc[nt][2]*inv1, acc[nt][3]*inv1, hv, lv);
        g_ctx_hi[r0b + 8*512 + cu] = hv;  g_ctx_lo[r0b + 8*512 + cu] = lv;
    }
}

// ---------------------------------------------------------------------------
// Kernel 3: out = ctx @ Wo^T + bo, cp.async double-buffered.
// Stage layout (40960 B/stage): Ah@0 Al@10240 Bh@20480 Bl@30720 (10240 each)
// ---------------------------------------------------------------------------
#define O_STAGE 40960
#define O_SMEM  (2*O_STAGE)

__global__ __launch_bounds__(256) void outproj_mma(
    const float* __restrict__ bo, float* __restrict__ out)
{
    extern __shared__ char sm[];
    const int tid  = threadIdx.x;
    const int lane = tid & 31;
    const int wid  = tid >> 5;
    const int wm   = (wid >> 2) * 64;
    const int wn   = (wid & 3) * 32;
    const int row0 = blockIdx.x * 128;
    const int col0 = blockIdx.y * 128;
    const uint32_t smU = smem_u32(sm);

    const uint32_t* Wohi = g_in_hi + WOOFF;
    const uint32_t* Wolo = g_in_lo + WOOFF;

    float acc[4][4][4] = {};

    auto fill = [&](int ch, int s) {
        const int kbu = ch * (KCH/2);
        const uint32_t base = smU + s*O_STAGE;
        #pragma unroll
        for (int j = 0; j < 2; j++) {
            int gi = tid + j*256;
            int r = gi >> 2, g = gi & 3;
            uint32_t d = base + r*APITCHB + g*16;
            size_t ao = (size_t)(row0 + r)*512 + kbu + g*4;
            cpa16(d,          g_ctx_hi + ao);
            cpa16(d + 10240,  g_ctx_lo + ao);
            size_t wo = (size_t)(col0 + r)*512 + kbu + g*4;
            cpa16(d + 20480,  Wohi + wo);
            cpa16(d + 30720,  Wolo + wo);
        }
    };

    fill(0, 0);
    CPA_COMMIT();

    for (int ch = 0; ch < NCHK; ch++) {
        if (ch + 1 < NCHK) fill(ch + 1, (ch + 1) & 1);
        CPA_COMMIT();
        CPA_WAIT1();
        __syncthreads();

        const uint32_t base = smU + (ch & 1)*O_STAGE;
        const uint32_t aBh = base, aBl = base + 10240;
        const uint32_t bBh = base + 20480, bBl = base + 30720;

        #pragma unroll
        for (int ks = 0; ks < 2; ks++) {
            uint32_t Ah[4][4], Al[4][4], Bh[4][2], Bl[4][2];
            int am = wm + (lane & 7) + ((lane >> 3) & 1) * 8;
            int ag = ks*2 + (lane >> 4);
            uint32_t aoff = am*APITCHB + ag*16;
            #pragma unroll
            for (int mt = 0; mt < 4; mt++) {
                ldmA4(aBh + aoff + mt*16*APITCHB, Ah[mt]);
                ldmA4(aBl + aoff + mt*16*APITCHB, Al[mt]);
            }
            int bn = wn + (lane & 7);
            int bg = ks*2 + ((lane >> 3) & 1);
            uint32_t boff = bn*APITCHB + bg*16;
            #pragma unroll
            for (int nt = 0; nt < 4; nt++) {
                ldmB2(bBh + boff + nt*8*APITCHB, Bh[nt]);
                ldmB2(bBl + boff + nt*8*APITCHB, Bl[nt]);
            }
            #pragma unroll
            for (int mt = 0; mt < 4; mt++)
                #pragma unroll
                for (int nt = 0; nt < 4; nt++) {
                    mma16816(acc[mt][nt], Ah[mt], Bh[nt]);
                    mma16816(acc[mt][nt], Ah[mt], Bl[nt]);
                    mma16816(acc[mt][nt], Al[mt], Bh[nt]);
                }
        }
        __syncthreads();
    }

    #pragma unroll
    for (int mt = 0; mt < 4; mt++) {
        int m = row0 + wm + mt*16 + (lane >> 2);
        float* dst = out + (size_t)m*1024 + col0;
        #pragma unroll
        for (int nt = 0; nt < 4; nt++) {
            int col = wn + nt*8 + (lane & 3)*2;
            float b0v = bo[col0 + col], b1v = bo[col0 + col + 1];
            *(float2*)(dst + col) =
                make_float2(acc[mt][nt][0] + b0v, acc[mt][nt][1] + b1v);
            *(float2*)(dst + 8*1024 + col) =
                make_float2(acc[mt][nt][2] + b0v, acc[mt][nt][3] + b1v);
        }
    }
}

// ---------------------------------------------------------------------------
extern "C" void kernel_launch(void* const* d_in, const int* in_sizes, int n_in,
                              void* d_out, int out_size)
{
    const float* q  = (const float*)d_in[0];
    const float* k  = (const float*)d_in[1];
    const float* v  = (const float*)d_in[2];
    const float* Wq = (const float*)d_in[3];
    const float* Wk = (const float*)d_in[4];
    const float* Wv = (const float*)d_in[5];
    const float* Wo = (const float*)d_in[6];
    const float* bo = (const float*)d_in[7];
    float* out = (float*)d_out;

    cudaFuncSetAttribute(proj_mma,    cudaFuncAttributeMaxDynamicSharedMemorySize, P_SMEM);
    cudaFuncSetAttribute(attn_mma,    cudaFuncAttributeMaxDynamicSharedMemorySize, A_SMEM);
    cudaFuncSetAttribute(outproj_mma, cudaFuncAttributeMaxDynamicSharedMemorySize, O_SMEM);

    split_pre<<<2048, 256>>>(q,  QOFF,  2097152);
    split_pre<<<2048, 256>>>(k,  KOFF,  2097152);
    split_pre<<<2048, 256>>>(v,  VOFF,  2097152);
    split_pre<<<1024, 256>>>(Wq, WQOFF, 524288);
    split_pre<<<1024, 256>>>(Wk, WKOFF, 524288);
    split_pre<<<1024, 256>>>(Wv, WVOFF, 524288);
    split_pre<<<1024, 256>>>(Wo, WOOFF, 524288);

    proj_mma<<<dim3(Mn/128, Dn/128, 3), 256, P_SMEM>>>();
    attn_mma<<<dim3(Sn/64, Hn, Bn), 128, A_SMEM>>>();
    outproj_mma<<<dim3(Mn/128, Dn/128), 256, O_SMEM>>>(bo, out);
}

// round 13
// speedup vs baseline: 3.9955x; 1.0182x over previous
#include <cuda_runtime.h>
#include <cuda_fp16.h>
#include <cstdint>

// Problem constants
#define Bn  2
#define Sn  2048
#define Dn  1024
#define Hn  8
#define Mn  (Bn*Sn)   // 4096

// ---------------------------------------------------------------------------
// Pre-split input pools (fp16x2-packed hi/lo of every fp32 input)
// ---------------------------------------------------------------------------
#define QOFF  0
#define KOFF  2097152
#define VOFF  4194304
#define WQOFF 6291456
#define WKOFF 6815744
#define WVOFF 7340032
#define WOOFF 7864320
#define INTOT 8388608
__device__ uint32_t g_in_hi[INTOT];
__device__ uint32_t g_in_lo[INTOT];
// heads: rows of 64 u32 (=128 fp16).  Q/K/V hi+lo (QK path needs 2-word);
// ctx hi-only (value path, un-amplified).
__device__ uint32_t g_qh_hi[Bn*Hn*Sn*64];
__device__ uint32_t g_qh_lo[Bn*Hn*Sn*64];
__device__ uint32_t g_kh_hi[Bn*Hn*Sn*64];
__device__ uint32_t g_kh_lo[Bn*Hn*Sn*64];
__device__ uint32_t g_vh_hi[Bn*Hn*Sn*64];
__device__ uint32_t g_vh_lo[Bn*Hn*Sn*64];
__device__ uint32_t g_ctx_hi[Mn*512];

// ===========================================================================
// helpers
// ===========================================================================
__device__ __forceinline__ uint32_t smem_u32(const void* p) {
    uint32_t a;
    asm("{ .reg .u64 t; cvta.to.shared.u64 t, %1; cvt.u32.u64 %0, t; }" : "=r"(a) : "l"(p));
    return a;
}
__device__ __forceinline__ void ldmA4(uint32_t addr, uint32_t* r) {
    asm volatile("ldmatrix.sync.aligned.m8n8.x4.shared.b16 {%0,%1,%2,%3}, [%4];"
                 : "=r"(r[0]), "=r"(r[1]), "=r"(r[2]), "=r"(r[3]) : "r"(addr));
}
__device__ __forceinline__ void ldmB2(uint32_t addr, uint32_t* r) {
    asm volatile("ldmatrix.sync.aligned.m8n8.x2.shared.b16 {%0,%1}, [%2];"
                 : "=r"(r[0]), "=r"(r[1]) : "r"(addr));
}
__device__ __forceinline__ void ldmB2t(uint32_t addr, uint32_t* r) {
    asm volatile("ldmatrix.sync.aligned.m8n8.x2.trans.shared.b16 {%0,%1}, [%2];"
                 : "=r"(r[0]), "=r"(r[1]) : "r"(addr));
}
// fp16 mma, fp32 accumulate
__device__ __forceinline__ void mma16816(float* c, const uint32_t* a, const uint32_t* b) {
    asm volatile(
        "mma.sync.aligned.m16n8k16.row.col.f32.f16.f16.f32 "
        "{%0,%1,%2,%3}, {%4,%5,%6,%7}, {%8,%9}, {%0,%1,%2,%3};"
        : "+f"(c[0]), "+f"(c[1]), "+f"(c[2]), "+f"(c[3])
        : "r"(a[0]), "r"(a[1]), "r"(a[2]), "r"(a[3]), "r"(b[0]), "r"(b[1]));
}
__device__ __forceinline__ uint32_t pack2h(float x0, float x1) {
    __half2 hp; hp.x = __float2half_rn(x0); hp.y = __float2half_rn(x1);
    return *(uint32_t*)&hp;
}
__device__ __forceinline__ void split2h(float x0, float x1, uint32_t& hi, uint32_t& lo) {
    __half h0 = __float2half_rn(x0);
    __half h1 = __float2half_rn(x1);
    __half l0 = __float2half_rn(x0 - __half2float(h0));
    __half l1 = __float2half_rn(x1 - __half2float(h1));
    __half2 hp; hp.x = h0; hp.y = h1;
    __half2 lp; lp.x = l0; lp.y = l1;
    hi = *(uint32_t*)&hp;  lo = *(uint32_t*)&lp;
}
// cp.async (Ampere-lineage, present in base sm_100)
__device__ __forceinline__ void cpa16(uint32_t dst, const void* src) {
    asm volatile("cp.async.cg.shared.global [%0], [%1], 16;" :: "r"(dst), "l"(src));
}
#define CPA_COMMIT() asm volatile("cp.async.commit_group;" ::: "memory")
#define CPA_WAIT1()  asm volatile("cp.async.wait_group 1;" ::: "memory")

#define APITCHB 80
#define KCH     32
#define NCHK    (Dn / KCH)

// ---------------------------------------------------------------------------
// Kernel 0: merged pre-split of all 7 fp32 inputs -> fp16 hi/lo pools
// ---------------------------------------------------------------------------
__global__ __launch_bounds__(256) void split_all(
    const float* __restrict__ q,  const float* __restrict__ k,
    const float* __restrict__ v,  const float* __restrict__ wq,
    const float* __restrict__ wk, const float* __restrict__ wv,
    const float* __restrict__ wo)
{
    int i = blockIdx.x * blockDim.x + threadIdx.x;
    int stride = gridDim.x * blockDim.x;
    for (; i < INTOT; i += stride) {
        const float* src; int off;
        if      (i < KOFF)  { src = q;  off = QOFF;  }
        else if (i < VOFF)  { src = k;  off = KOFF;  }
        else if (i < WQOFF) { src = v;  off = VOFF;  }
        else if (i < WKOFF) { src = wq; off = WQOFF; }
        else if (i < WVOFF) { src = wk; off = WKOFF; }
        else if (i < WOOFF) { src = wv; off = WVOFF; }
        else                { src = wo; off = WOOFF; }
        float2 x = ((const float2*)src)[i - off];
        split2h(x.x, x.y, g_in_hi[i], g_in_lo[i]);
    }
}

// ---------------------------------------------------------------------------
// Kernel 1: fused projections, cp.async double-buffered, fp16 hybrid.
// Q/K legs: A hi+lo, 3-term (QK path).  V leg: A hi-only compute, 2-term.
// Stage (36864 B): Ah@0 Al@10240 | Bh@20480 Bl@28672
// ---------------------------------------------------------------------------
#define P_STAGE 36864
#define P_SMEM  (2*P_STAGE)

__global__ __launch_bounds__(256) void proj_mma()
{
    extern __shared__ char sm[];
    const uint32_t *Ahi, *Alo, *Whi, *Wlo;
    uint32_t *Chi, *Clo; float oscale;
    if (blockIdx.z == 0)      { Ahi = g_in_hi+QOFF;  Alo = g_in_lo+QOFF;
                                Whi = g_in_hi+WQOFF; Wlo = g_in_lo+WQOFF;
                                Chi = g_qh_hi; Clo = g_qh_lo;
                                oscale = 0.08838834764831845f; }
    else if (blockIdx.z == 1) { Ahi = g_in_hi+KOFF;  Alo = g_in_lo+KOFF;
                                Whi = g_in_hi+WKOFF; Wlo = g_in_lo+WKOFF;
                                Chi = g_kh_hi; Clo = g_kh_lo; oscale = 1.0f; }
    else                      { Ahi = g_in_hi+VOFF;  Alo = g_in_lo+VOFF;
                                Whi = g_in_hi+WVOFF; Wlo = g_in_lo+WVOFF;
                                Chi = g_vh_hi; Clo = g_vh_lo; oscale = 1.0f; }
    const bool doAl = (blockIdx.z != 2);   // 3rd term only on Q/K legs

    const int tid  = threadIdx.x;
    const int lane = tid & 31;
    const int wid  = tid >> 5;
    const int wm   = (wid >> 2) * 64;
    const int wn   = (wid & 3) * 32;
    const int row0 = blockIdx.x * 128;
    const int col0u = blockIdx.y * 64;   // u32 col offset
    const uint32_t smU = smem_u32(sm);

    float acc[4][4][4] = {};

    auto fill = [&](int ch, int s) {
        const int kbu = ch * (KCH/2);
        const uint32_t base = smU + s*P_STAGE;
        #pragma unroll
        for (int j = 0; j < 2; j++) {
            int gi = tid + j*256;
            int r = gi >> 2, g = gi & 3;
            uint32_t d = base + r*APITCHB + g*16;
            size_t so = (size_t)(row0 + r)*512 + kbu + g*4;
            cpa16(d,          Ahi + so);
            cpa16(d + 10240,  Alo + so);
        }
        #pragma unroll
        for (int j = 0; j < 2; j++) {
            int gi = tid + j*256;
            int kr = gi >> 4, ng = gi & 15;
            uint32_t d = base + 20480 + kr*256 + ((ng ^ (kr & 7)) * 16);
            size_t so = (size_t)(ch*KCH + kr)*512 + col0u + ng*4;
            cpa16(d,         Whi + so);
            cpa16(d + 8192,  Wlo + so);
        }
    };

    fill(0, 0);
    CPA_COMMIT();

    for (int ch = 0; ch < NCHK; ch++) {
        if (ch + 1 < NCHK) fill(ch + 1, (ch + 1) & 1);
        CPA_COMMIT();
        CPA_WAIT1();
        __syncthreads();

        const uint32_t base = smU + (ch & 1)*P_STAGE;
        const uint32_t aBh = base, aBl = base + 10240;
        const uint32_t bBh = base + 20480, bBl = base + 28672;

        #pragma unroll
        for (int ks = 0; ks < 2; ks++) {
            uint32_t Ah[4][4], Al[4][4], Bh[4][2], Bl[4][2];
            int am = wm + (lane & 7) + ((lane >> 3) & 1) * 8;
            int ag = ks*2 + (lane >> 4);
            uint32_t aoff = am*APITCHB + ag*16;
            #pragma unroll
            for (int mt = 0; mt < 4; mt++) {
                ldmA4(aBh + aoff + mt*16*APITCHB, Ah[mt]);
                if (doAl) ldmA4(aBl + aoff + mt*16*APITCHB, Al[mt]);
            }
            int bk = ks*16 + (lane & 7) + ((lane >> 3) & 1) * 8;
            #pragma unroll
            for (int nt = 0; nt < 4; nt++) {
                int ngi = (wn >> 3) + nt;
                uint32_t boff = bk*256 + ((ngi ^ (bk & 7)) * 16);
                ldmB2t(bBh + boff, Bh[nt]);
                ldmB2t(bBl + boff, Bl[nt]);
            }
            #pragma unroll
            for (int mt = 0; mt < 4; mt++)
                #pragma unroll
                for (int nt = 0; nt < 4; nt++) {
                    mma16816(acc[mt][nt], Ah[mt], Bh[nt]);
                    mma16816(acc[mt][nt], Ah[mt], Bl[nt]);
                    if (doAl) mma16816(acc[mt][nt], Al[mt], Bh[nt]);
                }
        }
        __syncthreads();
    }

    // epilogue: fp16 hi+lo heads
    #pragma unroll
    for (int mt = 0; mt < 4; mt++) {
        int m  = row0 + wm + mt*16 + (lane >> 2);
        int b_ = m >> 11;
        int s_ = m & (Sn - 1);
        size_t rb = ((size_t)(b_*Hn + blockIdx.y)*Sn + s_) * 64;
        #pragma unroll
        for (int nt = 0; nt < 4; nt++) {
            int cu = ((wn + nt*8) >> 1) + (lane & 3);
            uint32_t hv, lv;
            split2h(acc[mt][nt][0]*oscale, acc[mt][nt][1]*oscale, hv, lv);
            Chi[rb + cu] = hv;  Clo[rb + cu] = lv;
            split2h(acc[mt][nt][2]*oscale, acc[mt][nt][3]*oscale, hv, lv);
            Chi[rb + 8*64 + cu] = hv;  Clo[rb + 8*64 + cu] = lv;
        }
    }
}

// ---------------------------------------------------------------------------
// Kernel 2: flash attention, cp.async double-buffered, fp16 hybrid.
// QK: Q hi+lo register fragments, 3-term.  PV: P hi-only, V hi+lo, 2-term.
// Stage (32768 B) at smU + s*32768: KH@0 KL@8192 VH@16384 VL@24576
// ---------------------------------------------------------------------------
#define A_SMEM (2*32768)   // 65536

__global__ __launch_bounds__(128) void attn_mma()
{
    extern __shared__ char sm[];
    const int tid  = threadIdx.x;
    const int lane = tid & 31;
    const int wid  = tid >> 5;
    const int h = blockIdx.y, b = blockIdx.z;
    const int q0 = blockIdx.x * 64;

    const size_t hb = ((size_t)(b*Hn + h)) * Sn * 64;
    const uint32_t* Qhi = g_qh_hi + hb;
    const uint32_t* Qlo = g_qh_lo + hb;
    const uint32_t* Khi = g_kh_hi + hb;
    const uint32_t* Klo = g_kh_lo + hb;
    const uint32_t* Vhi = g_vh_hi + hb;
    const uint32_t* Vlo = g_vh_lo + hb;

    const uint32_t smU = smem_u32(sm);

    // ---- stage Q hi+lo through stage-1 region (16KB each), hoist to regs
    #pragma unroll
    for (int j = 0; j < 8; j++) {
        int gi = tid + j*128;
        int r  = gi >> 4, g = gi & 15;
        int so = r*256 + ((g ^ (r & 7)) * 16);
        size_t go = (size_t)(q0 + r)*64 + g*4;
        *(uint4*)(sm + 32768 + so)         = *(const uint4*)(Qhi + go);
        *(uint4*)(sm + 32768 + 16384 + so) = *(const uint4*)(Qlo + go);
    }
    __syncthreads();
    uint32_t Ah[8][4], Al[8][4];
    const int arow = wid*16 + (lane & 7) + ((lane >> 3) & 1) * 8;
    #pragma unroll
    for (int ks = 0; ks < 8; ks++) {
        int agrp = ks*2 + (lane >> 4);
        uint32_t ao = arow*256 + ((agrp ^ (lane & 7)) * 16);
        ldmA4(smU + 32768 + ao,         Ah[ks]);
        ldmA4(smU + 32768 + 16384 + ao, Al[ks]);
    }

    auto fill = [&](int kt, int s) {
        const uint32_t base = smU + s*32768;
        #pragma unroll
        for (int j = 0; j < 4; j++) {
            int gi = tid + j*128;
            int r  = gi >> 4, g = gi & 15;
            uint32_t so = r*256 + ((g ^ (r & 7)) * 16);
            size_t go = (size_t)(kt + r)*64 + g*4;
            cpa16(base + so,          Khi + go);
            cpa16(base + 8192 + so,   Klo + go);
            cpa16(base + 16384 + so,  Vhi + go);
            cpa16(base + 24576 + so,  Vlo + go);
        }
    };

    fill(0, 0);
    CPA_COMMIT();
    __syncthreads();   // Q-frag ldmatrix reads complete before stage-1 refill

    float acc[16][4] = {};
    float rm[2] = {-1.0e30f, -1.0e30f}, rl[2] = {0.0f, 0.0f};

    const int NKT = Sn / 32;
    for (int ch = 0; ch < NKT; ch++) {
        if (ch + 1 < NKT) fill((ch + 1) * 32, (ch + 1) & 1);
        CPA_COMMIT();
        CPA_WAIT1();
        __syncthreads();

        const uint32_t base = smU + (ch & 1)*32768;
        const uint32_t KH = base, KL = base + 8192, VH = base + 16384, VL = base + 24576;

        // ---- QK^T: 3-term (AhKh + AhKl + AlKh)
        float sc[4][4] = {};
        #pragma unroll
        for (int ks = 0; ks < 8; ks++) {
            int bgrp = ks*2 + ((lane >> 3) & 1);
            #pragma unroll
            for (int nt = 0; nt < 4; nt++) {
                uint32_t Bh[2], Bl[2];
                int brow = nt*8 + (lane & 7);
                uint32_t boff = brow*256 + ((bgrp ^ (lane & 7)) * 16);
                ldmB2(KH + boff, Bh);
                ldmB2(KL + boff, Bl);
                mma16816(sc[nt], Ah[ks], Bh);
                mma16816(sc[nt], Ah[ks], Bl);
                mma16816(sc[nt], Al[ks], Bh);
            }
        }

        // ---- online softmax (rows: set0 = lane>>2, set1 = +8)
        float mx0 = sc[0][0], mx1 = sc[0][2];
        #pragma unroll
        for (int nt = 0; nt < 4; nt++) {
            mx0 = fmaxf(mx0, fmaxf(sc[nt][0], sc[nt][1]));
            mx1 = fmaxf(mx1, fmaxf(sc[nt][2], sc[nt][3]));
        }
        mx0 = fmaxf(mx0, __shfl_xor_sync(0xffffffffu, mx0, 1));
        mx0 = fmaxf(mx0, __shfl_xor_sync(0xffffffffu, mx0, 2));
        mx1 = fmaxf(mx1, __shfl_xor_sync(0xffffffffu, mx1, 1));
        mx1 = fmaxf(mx1, __shfl_xor_sync(0xffffffffu, mx1, 2));
        float nm0 = fmaxf(rm[0], mx0), nm1 = fmaxf(rm[1], mx1);
        float cr0 = __expf(rm[0] - nm0), cr1 = __expf(rm[1] - nm1);
        rm[0] = nm0; rm[1] = nm1;
        float rs0 = 0.0f, rs1 = 0.0f;
        #pragma unroll
        for (int nt = 0; nt < 4; nt++) {
            sc[nt][0] = __expf(sc[nt][0] - nm0);
            sc[nt][1] = __expf(sc[nt][1] - nm0);
            sc[nt][2] = __expf(sc[nt][2] - nm1);
            sc[nt][3] = __expf(sc[nt][3] - nm1);
            rs0 += sc[nt][0] + sc[nt][1];
            rs1 += sc[nt][2] + sc[nt][3];
        }
        rs0 += __shfl_xor_sync(0xffffffffu, rs0, 1);
        rs0 += __shfl_xor_sync(0xffffffffu, rs0, 2);
        rs1 += __shfl_xor_sync(0xffffffffu, rs1, 1);
        rs1 += __shfl_xor_sync(0xffffffffu, rs1, 2);
        rl[0] = rl[0]*cr0 + rs0;
        rl[1] = rl[1]*cr1 + rs1;
        #pragma unroll
        for (int nt = 0; nt < 16; nt++) {
            acc[nt][0] *= cr0; acc[nt][1] *= cr0;
            acc[nt][2] *= cr1; acc[nt][3] *= cr1;
        }

        // ---- P -> fp16-hi A-fragments in registers (acc layout == A layout)
        uint32_t Ph[2][4];
        #pragma unroll
        for (int s = 0; s < 2; s++) {
            Ph[s][0] = pack2h(sc[2*s][0],   sc[2*s][1]);
            Ph[s][1] = pack2h(sc[2*s][2],   sc[2*s][3]);
            Ph[s][2] = pack2h(sc[2*s+1][0], sc[2*s+1][1]);
            Ph[s][3] = pack2h(sc[2*s+1][2], sc[2*s+1][3]);
        }

        // ---- PV (P hi-only; V hi+lo): 2-term
        #pragma unroll
        for (int s = 0; s < 2; s++) {
            int brow = s*16 + (lane & 7) + ((lane >> 3) & 1) * 8;
            #pragma unroll
            for (int nt = 0; nt < 16; nt++) {
                uint32_t Bh[2], Bl[2];
                uint32_t boff = brow*256 + ((nt ^ (lane & 7)) * 16);
                ldmB2t(VH + boff, Bh);
                ldmB2t(VL + boff, Bl);
                mma16816(acc[nt], Ph[s], Bh);
                mma16816(acc[nt], Ph[s], Bl);
            }
        }
        __syncthreads();
    }

    // ---- epilogue: normalize, write ctx hi (concat layout)
    float inv0 = 1.0f / rl[0], inv1 = 1.0f / rl[1];
    int m0 = q0 + wid*16 + (lane >> 2);
    size_t r0b = (size_t)(b*Sn + m0)*512 + h*64;
    #pragma unroll
    for (int nt = 0; nt < 16; nt++) {
        int cu = nt*4 + (lane & 3);
        g_ctx_hi[r0b + cu]         = pack2h(acc[nt][0]*inv0, acc[nt][1]*inv0);
        g_ctx_hi[r0b + 8*512 + cu] = pack2h(acc[nt][2]*inv1, acc[nt][3]*inv1);
    }
}

// ---------------------------------------------------------------------------
// Kernel 3: out = ctx @ Wo^T + bo, cp.async double-buffered, fp16 (A hi-only).
// Stage (30720 B): Ah@0 (10240) | Bh@10240 (10240) | Bl@20480 (10240)
// ---------------------------------------------------------------------------
#define O_STAGE 30720
#define O_SMEM  (2*O_STAGE)

__global__ __launch_bounds__(256) void outproj_mma(
    const float* __restrict__ bo, float* __restrict__ out)
{
    extern __shared__ char sm[];
    const int tid  = threadIdx.x;
    const int lane = tid & 31;
    const int wid  = tid >> 5;
    const int wm   = (wid >> 2) * 64;
    const int wn   = (wid & 3) * 32;
    const int row0 = blockIdx.x * 128;
    const int col0 = blockIdx.y * 128;
    const uint32_t smU = smem_u32(sm);

    const uint32_t* Wohi = g_in_hi + WOOFF;
    const uint32_t* Wolo = g_in_lo + WOOFF;

    float acc[4][4][4] = {};

    auto fill = [&](int ch, int s) {
        const int kbu = ch * (KCH/2);
        const uint32_t base = smU + s*O_STAGE;
        #pragma unroll
        for (int j = 0; j < 2; j++) {
            int gi = tid + j*256;
            int r = gi >> 2, g = gi & 3;
            uint32_t d = base + r*APITCHB + g*16;
            cpa16(d, g_ctx_hi + (size_t)(row0 + r)*512 + kbu + g*4);
            size_t wo = (size_t)(col0 + r)*512 + kbu + g*4;
            cpa16(d + 10240,  Wohi + wo);
            cpa16(d + 20480,  Wolo + wo);
        }
    };

    fill(0, 0);
    CPA_COMMIT();

    for (int ch = 0; ch < NCHK; ch++) {
        if (ch + 1 < NCHK) fill(ch + 1, (ch + 1) & 1);
        CPA_COMMIT();
        CPA_WAIT1();
        __syncthreads();

        const uint32_t base = smU + (ch & 1)*O_STAGE;
        const uint32_t aBh = base;
        const uint32_t bBh = base + 10240, bBl = base + 20480;

        #pragma unroll
        for (int ks = 0; ks < 2; ks++) {
            uint32_t Ah[4][4], Bh[4][2], Bl[4][2];
            int am = wm + (lane & 7) + ((lane >> 3) & 1) * 8;
            int ag = ks*2 + (lane >> 4);
            uint32_t aoff = am*APITCHB + ag*16;
            #pragma unroll
            for (int mt = 0; mt < 4; mt++)
                ldmA4(aBh + aoff + mt*16*APITCHB, Ah[mt]);
            int bn = wn + (lane & 7);
            int bg = ks*2 + ((lane >> 3) & 1);
            uint32_t boff = bn*APITCHB + bg*16;
            #pragma unroll
            for (int nt = 0; nt < 4; nt++) {
                ldmB2(bBh + boff + nt*8*APITCHB, Bh[nt]);
                ldmB2(bBl + boff + nt*8*APITCHB, Bl[nt]);
            }
            #pragma unroll
            for (int mt = 0; mt < 4; mt++)
                #pragma unroll
                for (int nt = 0; nt < 4; nt++) {
                    mma16816(acc[mt][nt], Ah[mt], Bh[nt]);
                    mma16816(acc[mt][nt], Ah[mt], Bl[nt]);
                }
        }
        __syncthreads();
    }

    #pragma unroll
    for (int mt = 0; mt < 4; mt++) {
        int m = row0 + wm + mt*16 + (lane >> 2);
        float* dst = out + (size_t)m*1024 + col0;
        #pragma unroll
        for (int nt = 0; nt < 4; nt++) {
            int col = wn + nt*8 + (lane & 3)*2;
            float b0v = bo[col0 + col], b1v = bo[col0 + col + 1];
            *(float2*)(dst + col) =
                make_float2(acc[mt][nt][0] + b0v, acc[mt][nt][1] + b1v);
            *(float2*)(dst + 8*1024 + col) =
                make_float2(acc[mt][nt][2] + b0v, acc[mt][nt][3] + b1v);
        }
    }
}

// ---------------------------------------------------------------------------
extern "C" void kernel_launch(void* const* d_in, const int* in_sizes, int n_in,
                              void* d_out, int out_size)
{
    const float* q  = (const float*)d_in[0];
    const float* k  = (const float*)d_in[1];
    const float* v  = (const float*)d_in[2];
    const float* Wq = (const float*)d_in[3];
    const float* Wk = (const float*)d_in[4];
    const float* Wv = (const float*)d_in[5];
    const float* Wo = (const float*)d_in[6];
    const float* bo = (const float*)d_in[7];
    float* out = (float*)d_out;

    cudaFuncSetAttribute(proj_mma,    cudaFuncAttributeMaxDynamicSharedMemorySize, P_SMEM);
    cudaFuncSetAttribute(attn_mma,    cudaFuncAttributeMaxDynamicSharedMemorySize, A_SMEM);
    cudaFuncSetAttribute(outproj_mma, cudaFuncAttributeMaxDynamicSharedMemorySize, O_SMEM);

    split_all<<<4096, 256>>>(q, k, v, Wq, Wk, Wv, Wo);
    proj_mma<<<dim3(Mn/128, Dn/128, 3), 256, P_SMEM>>>();
    attn_mma<<<dim3(Sn/64, Hn, Bn), 128, A_SMEM>>>();
    outproj_mma<<<dim3(Mn/128, Dn/128), 256, O_SMEM>>>(bo, out);
}

// round 14
// speedup vs baseline: 4.1586x; 1.0408x over previous
#include <cuda_runtime.h>
#include <cuda_fp16.h>
#include <cstdint>

// Problem constants
#define Bn  2
#define Sn  2048
#define Dn  1024
#define Hn  8
#define Mn  (Bn*Sn)   // 4096

// ---------------------------------------------------------------------------
// Pre-split input pools (fp16x2-packed hi/lo of every fp32 input)
// ---------------------------------------------------------------------------
#define QOFF  0
#define KOFF  2097152
#define VOFF  4194304
#define WQOFF 6291456
#define WKOFF 6815744
#define WVOFF 7340032
#define WOOFF 7864320
#define INTOT 8388608
__device__ uint32_t g_in_hi[INTOT];
__device__ uint32_t g_in_lo[INTOT];
// heads: rows of 64 u32 (=128 fp16).  Q/K/V hi+lo (QK path needs 2-word);
// ctx hi-only (value path, un-amplified).
__device__ uint32_t g_qh_hi[Bn*Hn*Sn*64];
__device__ uint32_t g_qh_lo[Bn*Hn*Sn*64];
__device__ uint32_t g_kh_hi[Bn*Hn*Sn*64];
__device__ uint32_t g_kh_lo[Bn*Hn*Sn*64];
__device__ uint32_t g_vh_hi[Bn*Hn*Sn*64];
__device__ uint32_t g_vh_lo[Bn*Hn*Sn*64];
__device__ uint32_t g_ctx_hi[Mn*512];

// ===========================================================================
// helpers
// ===========================================================================
__device__ __forceinline__ uint32_t smem_u32(const void* p) {
    uint32_t a;
    asm("{ .reg .u64 t; cvta.to.shared.u64 t, %1; cvt.u32.u64 %0, t; }" : "=r"(a) : "l"(p));
    return a;
}
__device__ __forceinline__ void ldmA4(uint32_t addr, uint32_t* r) {
    asm volatile("ldmatrix.sync.aligned.m8n8.x4.shared.b16 {%0,%1,%2,%3}, [%4];"
                 : "=r"(r[0]), "=r"(r[1]), "=r"(r[2]), "=r"(r[3]) : "r"(addr));
}
__device__ __forceinline__ void ldmB2(uint32_t addr, uint32_t* r) {
    asm volatile("ldmatrix.sync.aligned.m8n8.x2.shared.b16 {%0,%1}, [%2];"
                 : "=r"(r[0]), "=r"(r[1]) : "r"(addr));
}
__device__ __forceinline__ void ldmB2t(uint32_t addr, uint32_t* r) {
    asm volatile("ldmatrix.sync.aligned.m8n8.x2.trans.shared.b16 {%0,%1}, [%2];"
                 : "=r"(r[0]), "=r"(r[1]) : "r"(addr));
}
// fp16 mma, fp32 accumulate
__device__ __forceinline__ void mma16816(float* c, const uint32_t* a, const uint32_t* b) {
    asm volatile(
        "mma.sync.aligned.m16n8k16.row.col.f32.f16.f16.f32 "
        "{%0,%1,%2,%3}, {%4,%5,%6,%7}, {%8,%9}, {%0,%1,%2,%3};"
        : "+f"(c[0]), "+f"(c[1]), "+f"(c[2]), "+f"(c[3])
        : "r"(a[0]), "r"(a[1]), "r"(a[2]), "r"(a[3]), "r"(b[0]), "r"(b[1]));
}
__device__ __forceinline__ uint32_t pack2h(float x0, float x1) {
    __half2 hp; hp.x = __float2half_rn(x0); hp.y = __float2half_rn(x1);
    return *(uint32_t*)&hp;
}
__device__ __forceinline__ void split2h(float x0, float x1, uint32_t& hi, uint32_t& lo) {
    __half h0 = __float2half_rn(x0);
    __half h1 = __float2half_rn(x1);
    __half l0 = __float2half_rn(x0 - __half2float(h0));
    __half l1 = __float2half_rn(x1 - __half2float(h1));
    __half2 hp; hp.x = h0; hp.y = h1;
    __half2 lp; lp.x = l0; lp.y = l1;
    hi = *(uint32_t*)&hp;  lo = *(uint32_t*)&lp;
}
// cp.async (Ampere-lineage, present in base sm_100)
__device__ __forceinline__ void cpa16(uint32_t dst, const void* src) {
    asm volatile("cp.async.cg.shared.global [%0], [%1], 16;" :: "r"(dst), "l"(src));
}
#define CPA_COMMIT() asm volatile("cp.async.commit_group;" ::: "memory")
#define CPA_WAIT1()  asm volatile("cp.async.wait_group 1;" ::: "memory")

#define APITCHB 80
#define KCH     32
#define NCHK    (Dn / KCH)

// ---------------------------------------------------------------------------
// Kernel 0: merged pre-split of all 7 fp32 inputs -> fp16 hi/lo pools
// ---------------------------------------------------------------------------
__global__ __launch_bounds__(256) void split_all(
    const float* __restrict__ q,  const float* __restrict__ k,
    const float* __restrict__ v,  const float* __restrict__ wq,
    const float* __restrict__ wk, const float* __restrict__ wv,
    const float* __restrict__ wo)
{
    int i = blockIdx.x * blockDim.x + threadIdx.x;
    int stride = gridDim.x * blockDim.x;
    for (; i < INTOT; i += stride) {
        const float* src; int off;
        if      (i < KOFF)  { src = q;  off = QOFF;  }
        else if (i < VOFF)  { src = k;  off = KOFF;  }
        else if (i < WQOFF) { src = v;  off = VOFF;  }
        else if (i < WKOFF) { src = wq; off = WQOFF; }
        else if (i < WVOFF) { src = wk; off = WKOFF; }
        else if (i < WOOFF) { src = wv; off = WVOFF; }
        else                { src = wo; off = WOOFF; }
        float2 x = ((const float2*)src)[i - off];
        split2h(x.x, x.y, g_in_hi[i], g_in_lo[i]);
    }
}

// ---------------------------------------------------------------------------
// Kernel 1: fused projections, cp.async double-buffered, fp16 hybrid.
// Q/K legs: A hi+lo, 3-term (QK path).  V leg: A hi-only compute, 2-term.
// Stage (36864 B): Ah@0 Al@10240 | Bh@20480 Bl@28672
// __launch_bounds__(256, 2): cap regs at 128 -> 2 CTAs/SM (smem 147KB OK).
// ---------------------------------------------------------------------------
#define P_STAGE 36864
#define P_SMEM  (2*P_STAGE)

__global__ __launch_bounds__(256, 2) void proj_mma()
{
    extern __shared__ char sm[];
    const uint32_t *Ahi, *Alo, *Whi, *Wlo;
    uint32_t *Chi, *Clo; float oscale;
    if (blockIdx.z == 0)      { Ahi = g_in_hi+QOFF;  Alo = g_in_lo+QOFF;
                                Whi = g_in_hi+WQOFF; Wlo = g_in_lo+WQOFF;
                                Chi = g_qh_hi; Clo = g_qh_lo;
                                oscale = 0.08838834764831845f; }
    else if (blockIdx.z == 1) { Ahi = g_in_hi+KOFF;  Alo = g_in_lo+KOFF;
                                Whi = g_in_hi+WKOFF; Wlo = g_in_lo+WKOFF;
                                Chi = g_kh_hi; Clo = g_kh_lo; oscale = 1.0f; }
    else                      { Ahi = g_in_hi+VOFF;  Alo = g_in_lo+VOFF;
                                Whi = g_in_hi+WVOFF; Wlo = g_in_lo+WVOFF;
                                Chi = g_vh_hi; Clo = g_vh_lo; oscale = 1.0f; }
    const bool doAl = (blockIdx.z != 2);   // 3rd term only on Q/K legs

    const int tid  = threadIdx.x;
    const int lane = tid & 31;
    const int wid  = tid >> 5;
    const int wm   = (wid >> 2) * 64;
    const int wn   = (wid & 3) * 32;
    const int row0 = blockIdx.x * 128;
    const int col0u = blockIdx.y * 64;   // u32 col offset
    const uint32_t smU = smem_u32(sm);

    float acc[4][4][4] = {};

    auto fill = [&](int ch, int s) {
        const int kbu = ch * (KCH/2);
        const uint32_t base = smU + s*P_STAGE;
        #pragma unroll
        for (int j = 0; j < 2; j++) {
            int gi = tid + j*256;
            int r = gi >> 2, g = gi & 3;
            uint32_t d = base + r*APITCHB + g*16;
            size_t so = (size_t)(row0 + r)*512 + kbu + g*4;
            cpa16(d,          Ahi + so);
            cpa16(d + 10240,  Alo + so);
        }
        #pragma unroll
        for (int j = 0; j < 2; j++) {
            int gi = tid + j*256;
            int kr = gi >> 4, ng = gi & 15;
            uint32_t d = base + 20480 + kr*256 + ((ng ^ (kr & 7)) * 16);
            size_t so = (size_t)(ch*KCH + kr)*512 + col0u + ng*4;
            cpa16(d,         Whi + so);
            cpa16(d + 8192,  Wlo + so);
        }
    };

    fill(0, 0);
    CPA_COMMIT();

    for (int ch = 0; ch < NCHK; ch++) {
        if (ch + 1 < NCHK) fill(ch + 1, (ch + 1) & 1);
        CPA_COMMIT();
        CPA_WAIT1();
        __syncthreads();

        const uint32_t base = smU + (ch & 1)*P_STAGE;
        const uint32_t aBh = base, aBl = base + 10240;
        const uint32_t bBh = base + 20480, bBl = base + 28672;

        #pragma unroll
        for (int ks = 0; ks < 2; ks++) {
            uint32_t Ah[4][4], Al[4][4], Bh[4][2], Bl[4][2];
            int am = wm + (lane & 7) + ((lane >> 3) & 1) * 8;
            int ag = ks*2 + (lane >> 4);
            uint32_t aoff = am*APITCHB + ag*16;
            #pragma unroll
            for (int mt = 0; mt < 4; mt++) {
                ldmA4(aBh + aoff + mt*16*APITCHB, Ah[mt]);
                if (doAl) ldmA4(aBl + aoff + mt*16*APITCHB, Al[mt]);
            }
            int bk = ks*16 + (lane & 7) + ((lane >> 3) & 1) * 8;
            #pragma unroll
            for (int nt = 0; nt < 4; nt++) {
                int ngi = (wn >> 3) + nt;
                uint32_t boff = bk*256 + ((ngi ^ (bk & 7)) * 16);
                ldmB2t(bBh + boff, Bh[nt]);
                ldmB2t(bBl + boff, Bl[nt]);
            }
            #pragma unroll
            for (int mt = 0; mt < 4; mt++)
                #pragma unroll
                for (int nt = 0; nt < 4; nt++) {
                    mma16816(acc[mt][nt], Ah[mt], Bh[nt]);
                    mma16816(acc[mt][nt], Ah[mt], Bl[nt]);
                    if (doAl) mma16816(acc[mt][nt], Al[mt], Bh[nt]);
                }
        }
        __syncthreads();
    }

    // epilogue: fp16 hi+lo heads
    #pragma unroll
    for (int mt = 0; mt < 4; mt++) {
        int m  = row0 + wm + mt*16 + (lane >> 2);
        int b_ = m >> 11;
        int s_ = m & (Sn - 1);
        size_t rb = ((size_t)(b_*Hn + blockIdx.y)*Sn + s_) * 64;
        #pragma unroll
        for (int nt = 0; nt < 4; nt++) {
            int cu = ((wn + nt*8) >> 1) + (lane & 3);
            uint32_t hv, lv;
            split2h(acc[mt][nt][0]*oscale, acc[mt][nt][1]*oscale, hv, lv);
            Chi[rb + cu] = hv;  Clo[rb + cu] = lv;
            split2h(acc[mt][nt][2]*oscale, acc[mt][nt][3]*oscale, hv, lv);
            Chi[rb + 8*64 + cu] = hv;  Clo[rb + 8*64 + cu] = lv;
        }
    }
}

// ---------------------------------------------------------------------------
// Kernel 2: flash attention, cp.async double-buffered, fp16 hybrid.
// QK: Q hi+lo register fragments, 3-term.  PV: P hi-only, V hi+lo, 2-term.
// Stage (32768 B) at smU + s*32768: KH@0 KL@8192 VH@16384 VL@24576
// __launch_bounds__(128, 3): cap regs at 170 -> 3 CTAs/SM (smem 192KB OK).
// ---------------------------------------------------------------------------
#define A_SMEM (2*32768)   // 65536

__global__ __launch_bounds__(128, 3) void attn_mma()
{
    extern __shared__ char sm[];
    const int tid  = threadIdx.x;
    const int lane = tid & 31;
    const int wid  = tid >> 5;
    const int h = blockIdx.y, b = blockIdx.z;
    const int q0 = blockIdx.x * 64;

    const size_t hb = ((size_t)(b*Hn + h)) * Sn * 64;
    const uint32_t* Qhi = g_qh_hi + hb;
    const uint32_t* Qlo = g_qh_lo + hb;
    const uint32_t* Khi = g_kh_hi + hb;
    const uint32_t* Klo = g_kh_lo + hb;
    const uint32_t* Vhi = g_vh_hi + hb;
    const uint32_t* Vlo = g_vh_lo + hb;

    const uint32_t smU = smem_u32(sm);

    // ---- stage Q hi+lo through stage-1 region (16KB each), hoist to regs
    #pragma unroll
    for (int j = 0; j < 8; j++) {
        int gi = tid + j*128;
        int r  = gi >> 4, g = gi & 15;
        int so = r*256 + ((g ^ (r & 7)) * 16);
        size_t go = (size_t)(q0 + r)*64 + g*4;
        *(uint4*)(sm + 32768 + so)         = *(const uint4*)(Qhi + go);
        *(uint4*)(sm + 32768 + 16384 + so) = *(const uint4*)(Qlo + go);
    }
    __syncthreads();
    uint32_t Ah[8][4], Al[8][4];
    const int arow = wid*16 + (lane & 7) + ((lane >> 3) & 1) * 8;
    #pragma unroll
    for (int ks = 0; ks < 8; ks++) {
        int agrp = ks*2 + (lane >> 4);
        uint32_t ao = arow*256 + ((agrp ^ (lane & 7)) * 16);
        ldmA4(smU + 32768 + ao,         Ah[ks]);
        ldmA4(smU + 32768 + 16384 + ao, Al[ks]);
    }

    auto fill = [&](int kt, int s) {
        const uint32_t base = smU + s*32768;
        #pragma unroll
        for (int j = 0; j < 4; j++) {
            int gi = tid + j*128;
            int r  = gi >> 4, g = gi & 15;
            uint32_t so = r*256 + ((g ^ (r & 7)) * 16);
            size_t go = (size_t)(kt + r)*64 + g*4;
            cpa16(base + so,          Khi + go);
            cpa16(base + 8192 + so,   Klo + go);
            cpa16(base + 16384 + so,  Vhi + go);
            cpa16(base + 24576 + so,  Vlo + go);
        }
    };

    fill(0, 0);
    CPA_COMMIT();
    __syncthreads();   // Q-frag ldmatrix reads complete before stage-1 refill

    float acc[16][4] = {};
    float rm[2] = {-1.0e30f, -1.0e30f}, rl[2] = {0.0f, 0.0f};

    const int NKT = Sn / 32;
    for (int ch = 0; ch < NKT; ch++) {
        if (ch + 1 < NKT) fill((ch + 1) * 32, (ch + 1) & 1);
        CPA_COMMIT();
        CPA_WAIT1();
        __syncthreads();

        const uint32_t base = smU + (ch & 1)*32768;
        const uint32_t KH = base, KL = base + 8192, VH = base + 16384, VL = base + 24576;

        // ---- QK^T: 3-term (AhKh + AhKl + AlKh)
        float sc[4][4] = {};
        #pragma unroll
        for (int ks = 0; ks < 8; ks++) {
            int bgrp = ks*2 + ((lane >> 3) & 1);
            #pragma unroll
            for (int nt = 0; nt < 4; nt++) {
                uint32_t Bh[2], Bl[2];
                int brow = nt*8 + (lane & 7);
                uint32_t boff = brow*256 + ((bgrp ^ (lane & 7)) * 16);
                ldmB2(KH + boff, Bh);
                ldmB2(KL + boff, Bl);
                mma16816(sc[nt], Ah[ks], Bh);
                mma16816(sc[nt], Ah[ks], Bl);
                mma16816(sc[nt], Al[ks], Bh);
            }
        }

        // ---- online softmax (rows: set0 = lane>>2, set1 = +8)
        float mx0 = sc[0][0], mx1 = sc[0][2];
        #pragma unroll
        for (int nt = 0; nt < 4; nt++) {
            mx0 = fmaxf(mx0, fmaxf(sc[nt][0], sc[nt][1]));
            mx1 = fmaxf(mx1, fmaxf(sc[nt][2], sc[nt][3]));
        }
        mx0 = fmaxf(mx0, __shfl_xor_sync(0xffffffffu, mx0, 1));
        mx0 = fmaxf(mx0, __shfl_xor_sync(0xffffffffu, mx0, 2));
        mx1 = fmaxf(mx1, __shfl_xor_sync(0xffffffffu, mx1, 1));
        mx1 = fmaxf(mx1, __shfl_xor_sync(0xffffffffu, mx1, 2));
        float nm0 = fmaxf(rm[0], mx0), nm1 = fmaxf(rm[1], mx1);
        float cr0 = __expf(rm[0] - nm0), cr1 = __expf(rm[1] - nm1);
        rm[0] = nm0; rm[1] = nm1;
        float rs0 = 0.0f, rs1 = 0.0f;
        #pragma unroll
        for (int nt = 0; nt < 4; nt++) {
            sc[nt][0] = __expf(sc[nt][0] - nm0);
            sc[nt][1] = __expf(sc[nt][1] - nm0);
            sc[nt][2] = __expf(sc[nt][2] - nm1);
            sc[nt][3] = __expf(sc[nt][3] - nm1);
            rs0 += sc[nt][0] + sc[nt][1];
            rs1 += sc[nt][2] + sc[nt][3];
        }
        rs0 += __shfl_xor_sync(0xffffffffu, rs0, 1);
        rs0 += __shfl_xor_sync(0xffffffffu, rs0, 2);
        rs1 += __shfl_xor_sync(0xffffffffu, rs1, 1);
        rs1 += __shfl_xor_sync(0xffffffffu, rs1, 2);
        rl[0] = rl[0]*cr0 + rs0;
        rl[1] = rl[1]*cr1 + rs1;
        #pragma unroll
        for (int nt = 0; nt < 16; nt++) {
            acc[nt][0] *= cr0; acc[nt][1] *= cr0;
            acc[nt][2] *= cr1; acc[nt][3] *= cr1;
        }

        // ---- P -> fp16-hi A-fragments in registers (acc layout == A layout)
        uint32_t Ph[2][4];
        #pragma unroll
        for (int s = 0; s < 2; s++) {
            Ph[s][0] = pack2h(sc[2*s][0],   sc[2*s][1]);
            Ph[s][1] = pack2h(sc[2*s][2],   sc[2*s][3]);
            Ph[s][2] = pack2h(sc[2*s+1][0], sc[2*s+1][1]);
            Ph[s][3] = pack2h(sc[2*s+1][2], sc[2*s+1][3]);
        }

        // ---- PV (P hi-only; V hi+lo): 2-term
        #pragma unroll
        for (int s = 0; s < 2; s++) {
            int brow = s*16 + (lane & 7) + ((lane >> 3) & 1) * 8;
            #pragma unroll
            for (int nt = 0; nt < 16; nt++) {
                uint32_t Bh[2], Bl[2];
                uint32_t boff = brow*256 + ((nt ^ (lane & 7)) * 16);
                ldmB2t(VH + boff, Bh);
                ldmB2t(VL + boff, Bl);
                mma16816(acc[nt], Ph[s], Bh);
                mma16816(acc[nt], Ph[s], Bl);
            }
        }
        __syncthreads();
    }

    // ---- epilogue: normalize, write ctx hi (concat layout)
    float inv0 = 1.0f / rl[0], inv1 = 1.0f / rl[1];
    int m0 = q0 + wid*16 + (lane >> 2);
    size_t r0b = (size_t)(b*Sn + m0)*512 + h*64;
    #pragma unroll
    for (int nt = 0; nt < 16; nt++) {
        int cu = nt*4 + (lane & 3);
        g_ctx_hi[r0b + cu]         = pack2h(acc[nt][0]*inv0, acc[nt][1]*inv0);
        g_ctx_hi[r0b + 8*512 + cu] = pack2h(acc[nt][2]*inv1, acc[nt][3]*inv1);
    }
}

// ---------------------------------------------------------------------------
// Kernel 3: out = ctx @ Wo^T + bo, cp.async double-buffered, fp16 (A hi-only).
// Stage (30720 B): Ah@0 (10240) | Bh@10240 (10240) | Bl@20480 (10240)
// __launch_bounds__(256, 2): cap regs at 128 -> 2 CTAs/SM.
// ---------------------------------------------------------------------------
#define O_STAGE 30720
#define O_SMEM  (2*O_STAGE)

__global__ __launch_bounds__(256, 2) void outproj_mma(
    const float* __restrict__ bo, float* __restrict__ out)
{
    extern __shared__ char sm[];
    const int tid  = threadIdx.x;
    const int lane = tid & 31;
    const int wid  = tid >> 5;
    const int wm   = (wid >> 2) * 64;
    const int wn   = (wid & 3) * 32;
    const int row0 = blockIdx.x * 128;
    const int col0 = blockIdx.y * 128;
    const uint32_t smU = smem_u32(sm);

    const uint32_t* Wohi = g_in_hi + WOOFF;
    const uint32_t* Wolo = g_in_lo + WOOFF;

    float acc[4][4][4] = {};

    auto fill = [&](int ch, int s) {
        const int kbu = ch * (KCH/2);
        const uint32_t base = smU + s*O_STAGE;
        #pragma unroll
        for (int j = 0; j < 2; j++) {
            int gi = tid + j*256;
            int r = gi >> 2, g = gi & 3;
            uint32_t d = base + r*APITCHB + g*16;
            cpa16(d, g_ctx_hi + (size_t)(row0 + r)*512 + kbu + g*4);
            size_t wo = (size_t)(col0 + r)*512 + kbu + g*4;
            cpa16(d + 10240,  Wohi + wo);
            cpa16(d + 20480,  Wolo + wo);
        }
    };

    fill(0, 0);
    CPA_COMMIT();

    for (int ch = 0; ch < NCHK; ch++) {
        if (ch + 1 < NCHK) fill(ch + 1, (ch + 1) & 1);
        CPA_COMMIT();
        CPA_WAIT1();
        __syncthreads();

        const uint32_t base = smU + (ch & 1)*O_STAGE;
        const uint32_t aBh = base;
        const uint32_t bBh = base + 10240, bBl = base + 20480;

        #pragma unroll
        for (int ks = 0; ks < 2; ks++) {
            uint32_t Ah[4][4], Bh[4][2], Bl[4][2];
            int am = wm + (lane & 7) + ((lane >> 3) & 1) * 8;
            int ag = ks*2 + (lane >> 4);
            uint32_t aoff = am*APITCHB + ag*16;
            #pragma unroll
            for (int mt = 0; mt < 4; mt++)
                ldmA4(aBh + aoff + mt*16*APITCHB, Ah[mt]);
            int bn = wn + (lane & 7);
            int bg = ks*2 + ((lane >> 3) & 1);
            uint32_t boff = bn*APITCHB + bg*16;
            #pragma unroll
            for (int nt = 0; nt < 4; nt++) {
                ldmB2(bBh + boff + nt*8*APITCHB, Bh[nt]);
                ldmB2(bBl + boff + nt*8*APITCHB, Bl[nt]);
            }
            #pragma unroll
            for (int mt = 0; mt < 4; mt++)
                #pragma unroll
                for (int nt = 0; nt < 4; nt++) {
                    mma16816(acc[mt][nt], Ah[mt], Bh[nt]);
                    mma16816(acc[mt][nt], Ah[mt], Bl[nt]);
                }
        }
        __syncthreads();
    }

    #pragma unroll
    for (int mt = 0; mt < 4; mt++) {
        int m = row0 + wm + mt*16 + (lane >> 2);
        float* dst = out + (size_t)m*1024 + col0;
        #pragma unroll
        for (int nt = 0; nt < 4; nt++) {
            int col = wn + nt*8 + (lane & 3)*2;
            float b0v = bo[col0 + col], b1v = bo[col0 + col + 1];
            *(float2*)(dst + col) =
                make_float2(acc[mt][nt][0] + b0v, acc[mt][nt][1] + b1v);
            *(float2*)(dst + 8*1024 + col) =
                make_float2(acc[mt][nt][2] + b0v, acc[mt][nt][3] + b1v);
        }
    }
}

// ---------------------------------------------------------------------------
extern "C" void kernel_launch(void* const* d_in, const int* in_sizes, int n_in,
                              void* d_out, int out_size)
{
    const float* q  = (const float*)d_in[0];
    const float* k  = (const float*)d_in[1];
    const float* v  = (const float*)d_in[2];
    const float* Wq = (const float*)d_in[3];
    const float* Wk = (const float*)d_in[4];
    const float* Wv = (const float*)d_in[5];
    const float* Wo = (const float*)d_in[6];
    const float* bo = (const float*)d_in[7];
    float* out = (float*)d_out;

    cudaFuncSetAttribute(proj_mma,    cudaFuncAttributeMaxDynamicSharedMemorySize, P_SMEM);
    cudaFuncSetAttribute(attn_mma,    cudaFuncAttributeMaxDynamicSharedMemorySize, A_SMEM);
    cudaFuncSetAttribute(outproj_mma, cudaFuncAttributeMaxDynamicSharedMemorySize, O_SMEM);

    split_all<<<4096, 256>>>(q, k, v, Wq, Wk, Wv, Wo);
    proj_mma<<<dim3(Mn/128, Dn/128, 3), 256, P_SMEM>>>();
    attn_mma<<<dim3(Sn/64, Hn, Bn), 128, A_SMEM>>>();
    outproj_mma<<<dim3(Mn/128, Dn/128), 256, O_SMEM>>>(bo, out);
}